// round 2
// baseline (speedup 1.0000x reference)
#include <cuda_runtime.h>
#include <cstdint>

#define MAX_N 50000
#define MAX_E 800000
#define HF    256      // H*F
#define NH    4
#define NF    64
#define NEG   0.2f

// ---------------- scratch (device globals: no allocations allowed) ----------
__device__ float g_proj [(size_t)MAX_N * HF];   // x @ W          [N,256]
__device__ float g_skipb[(size_t)MAX_N * HF];   // x @ skip_w     [N,256]
__device__ float g_ssrc [MAX_N * NH];           // per-head src scores
__device__ float g_strg [MAX_N * NH];           // per-head trg scores
__device__ int   g_deg  [MAX_N];
__device__ int   g_rowstart[MAX_N + 1];
__device__ int   g_pos  [MAX_N];
__device__ int   g_csr  [MAX_E];                // src node ids grouped by target

// ---------------- fp32 tiled SGEMM: C[M,256] = A[M,256] @ B[256,256] --------
#define BM 64
#define BN 64
#define BK 16

__global__ __launch_bounds__(256) void sgemm_kernel(
    const float* __restrict__ A, const float* __restrict__ B,
    float* __restrict__ C, int M)
{
    __shared__ __align__(16) float As[BK][BM + 4];  // transposed: As[k][m], row=272B (16B mult)
    __shared__ __align__(16) float Bs[BK][BN];      // Bs[k][n]

    const int tid = threadIdx.x;
    const int bm  = blockIdx.y;
    const int bn  = blockIdx.x;

    // A tile load: 64 rows x 16 k, one float4 along k per thread
    const int arow = tid >> 2;          // 0..63
    const int acol = (tid & 3) << 2;    // 0,4,8,12
    // B tile load: 16 k x 64 n, one float4 along n per thread
    const int brow = tid >> 4;          // 0..15
    const int bcol = (tid & 15) << 2;   // 0..60

    const int gr = bm * BM + arow;
    const float* Aptr = A + (size_t)gr * 256 + acol;
    const float* Bptr = B + (size_t)brow * 256 + bn * BN + bcol;

    const int ty = tid >> 4;            // 0..15 -> 4-row group
    const int tx = tid & 15;            // 0..15 -> 4-col group

    float acc[4][4];
#pragma unroll
    for (int i = 0; i < 4; i++)
#pragma unroll
        for (int j = 0; j < 4; j++) acc[i][j] = 0.f;

    for (int k0 = 0; k0 < 256; k0 += BK) {
        float4 av = make_float4(0.f, 0.f, 0.f, 0.f);
        if (gr < M) av = *(const float4*)(Aptr + k0);
        float4 bv = *(const float4*)(Bptr + (size_t)k0 * 256);

        As[acol + 0][arow] = av.x;
        As[acol + 1][arow] = av.y;
        As[acol + 2][arow] = av.z;
        As[acol + 3][arow] = av.w;
        *(float4*)&Bs[brow][bcol] = bv;
        __syncthreads();

#pragma unroll
        for (int kk = 0; kk < BK; kk++) {
            float4 a4 = *(const float4*)&As[kk][ty << 2];
            float4 b4 = *(const float4*)&Bs[kk][tx << 2];
            float a[4] = {a4.x, a4.y, a4.z, a4.w};
            float b[4] = {b4.x, b4.y, b4.z, b4.w};
#pragma unroll
            for (int i = 0; i < 4; i++)
#pragma unroll
                for (int j = 0; j < 4; j++) acc[i][j] += a[i] * b[j];
        }
        __syncthreads();
    }

    const int row0 = bm * BM + (ty << 2);
    const int col0 = bn * BN + (tx << 2);
#pragma unroll
    for (int i = 0; i < 4; i++) {
        if (row0 + i < M) {
            float4 v = make_float4(acc[i][0], acc[i][1], acc[i][2], acc[i][3]);
            *(float4*)&C[(size_t)(row0 + i) * 256 + col0] = v;
        }
    }
}

// ---------------- per-node per-head attention scores ------------------------
__global__ void score_kernel(const float* __restrict__ a_src,
                             const float* __restrict__ a_trg, int Nn)
{
    int w    = (blockIdx.x * blockDim.x + threadIdx.x) >> 5;
    int lane = threadIdx.x & 31;
    if (w >= Nn * NH) return;
    int n = w >> 2, h = w & 3;

    const float* pr = g_proj + (size_t)n * HF + h * NF;
    float p0 = pr[lane], p1 = pr[lane + 32];
    const float* as = a_src + h * NF;
    const float* at = a_trg + h * NF;
    float ss = p0 * as[lane] + p1 * as[lane + 32];
    float st = p0 * at[lane] + p1 * at[lane + 32];
#pragma unroll
    for (int o = 16; o; o >>= 1) {
        ss += __shfl_xor_sync(0xffffffffu, ss, o);
        st += __shfl_xor_sync(0xffffffffu, st, o);
    }
    if (lane == 0) {
        g_ssrc[n * NH + h] = ss;
        g_strg[n * NH + h] = st;
    }
}

// ---------------- CSR construction ------------------------------------------
__global__ void zero_deg_kernel(int Nn)
{
    int i = blockIdx.x * blockDim.x + threadIdx.x;
    if (i < Nn) g_deg[i] = 0;
}

__global__ void hist_kernel(const int* __restrict__ etrg, int E)
{
    int e = blockIdx.x * blockDim.x + threadIdx.x;
    if (e < E) atomicAdd(&g_deg[etrg[e]], 1);
}

__global__ void scan_kernel(int Nn)
{
    __shared__ int sh[1024];
    const int t = threadIdx.x;
    int carry = 0;
    for (int base = 0; base < Nn; base += 1024) {
        int i = base + t;
        int v = (i < Nn) ? g_deg[i] : 0;
        sh[t] = v;
        __syncthreads();
#pragma unroll
        for (int off = 1; off < 1024; off <<= 1) {
            int tv = (t >= off) ? sh[t - off] : 0;
            __syncthreads();
            sh[t] += tv;
            __syncthreads();
        }
        int excl  = sh[t] - v;
        int total = sh[1023];
        if (i < Nn) {
            g_rowstart[i] = carry + excl;
            g_pos[i]      = carry + excl;
        }
        carry += total;
        __syncthreads();
    }
    if (t == 0) g_rowstart[Nn] = carry;
}

__global__ void fill_kernel(const int* __restrict__ esrc,
                            const int* __restrict__ etrg, int E)
{
    int e = blockIdx.x * blockDim.x + threadIdx.x;
    if (e < E) {
        int tnode = etrg[e];
        int p = atomicAdd(&g_pos[tnode], 1);
        g_csr[p] = esrc[e];
    }
}

// ---------------- softmax-weighted aggregation + skip + bias + LeakyReLU ----
__global__ void agg_kernel(const float* __restrict__ bias,
                           float* __restrict__ out, int Nn)
{
    int w    = (blockIdx.x * blockDim.x + threadIdx.x) >> 5;
    int lane = threadIdx.x & 31;
    if (w >= Nn * NH) return;
    int n = w >> 2, h = w & 3;

    int s0 = g_rowstart[n];
    int s1 = g_rowstart[n + 1];
    float strg = g_strg[n * NH + h];

    // pass 1: softmax denominator over incoming edges
    float denom = 0.f;
    for (int i = s0 + lane; i < s1; i += 32) {
        int s  = g_csr[i];
        float e = g_ssrc[s * NH + h] + strg;
        e = (e > 0.f) ? e : NEG * e;
        denom += __expf(e);
    }
#pragma unroll
    for (int o = 16; o; o >>= 1) denom += __shfl_xor_sync(0xffffffffu, denom, o);
    float inv = 1.f / (denom + 1e-16f);

    // pass 2: weighted feature aggregation (gather, no atomics)
    float ax = 0.f, ay = 0.f;
    const float* projh = g_proj + h * NF;
    for (int i = s0; i < s1; i++) {
        int s  = g_csr[i];                       // broadcast load
        float e = g_ssrc[s * NH + h] + strg;     // broadcast load
        e = (e > 0.f) ? e : NEG * e;
        float wgt = __expf(e) * inv;
        float2 p = *(const float2*)(projh + (size_t)s * HF + (lane << 1));
        ax += wgt * p.x;
        ay += wgt * p.y;
    }

    size_t off = (size_t)n * HF + h * NF + (lane << 1);
    float2 sk = *(const float2*)(g_skipb + off);
    float bx = bias[h * NF + (lane << 1)];
    float by = bias[h * NF + (lane << 1) + 1];
    float ox = ax + sk.x + bx;
    float oy = ay + sk.y + by;
    ox = (ox > 0.f) ? ox : NEG * ox;
    oy = (oy > 0.f) ? oy : NEG * oy;
    *(float2*)(out + off) = make_float2(ox, oy);
}

// ---------------- launch ----------------------------------------------------
extern "C" void kernel_launch(void* const* d_in, const int* in_sizes, int n_in,
                              void* d_out, int out_size)
{
    const float* x      = (const float*)d_in[0];
    const float* W      = (const float*)d_in[1];
    const float* a_src  = (const float*)d_in[2];
    const float* a_trg  = (const float*)d_in[3];
    const float* skip_w = (const float*)d_in[4];
    const float* bias   = (const float*)d_in[5];
    const int*   esrc   = (const int*)d_in[6];
    const int*   etrg   = (const int*)d_in[7];
    float* out = (float*)d_out;

    const int Nn = in_sizes[0] / HF;   // 50000
    const int E  = in_sizes[6];        // 800000

    float *proj_p, *skip_p;
    cudaGetSymbolAddress((void**)&proj_p, g_proj);
    cudaGetSymbolAddress((void**)&skip_p, g_skipb);

    dim3 ggrid(HF / BN, (Nn + BM - 1) / BM);
    sgemm_kernel<<<ggrid, 256>>>(x, W,      proj_p, Nn);
    sgemm_kernel<<<ggrid, 256>>>(x, skip_w, skip_p, Nn);

    int warps = Nn * NH;
    score_kernel<<<(warps * 32 + 255) / 256, 256>>>(a_src, a_trg, Nn);

    zero_deg_kernel<<<(Nn + 255) / 256, 256>>>(Nn);
    hist_kernel<<<(E + 255) / 256, 256>>>(etrg, E);
    scan_kernel<<<1, 1024>>>(Nn);
    fill_kernel<<<(E + 255) / 256, 256>>>(esrc, etrg, E);

    agg_kernel<<<(warps * 32 + 255) / 256, 256>>>(bias, out, Nn);
}

// round 6
// speedup vs baseline: 2.2108x; 2.2108x over previous
#include <cuda_runtime.h>
#include <cuda_bf16.h>
#include <cstdint>

#define MAX_N 50000
#define MAX_E 800000
#define HF    256
#define NH    4
#define NF    64
#define NEG   0.2f

// ---------------- scratch (device globals; no allocations allowed) ----------
__device__ float g_proj [(size_t)MAX_N * HF];
__device__ float g_skipb[(size_t)MAX_N * HF];
__device__ float g_ssrc [MAX_N * NH];
__device__ float g_strg [MAX_N * NH];
__device__ int   g_deg  [MAX_N];
__device__ int   g_rowstart[MAX_N + 1];
__device__ int   g_pos  [MAX_N];
__device__ int   g_csr  [MAX_E];
__device__ __nv_bfloat16 g_xhi[(size_t)MAX_N * HF];
__device__ __nv_bfloat16 g_xlo[(size_t)MAX_N * HF];
__device__ __nv_bfloat16 g_bthi[512 * 256];   // [n 0..511][k] = (W | skip_w)^T
__device__ __nv_bfloat16 g_btlo[512 * 256];

// ---------------- PTX helpers (arch-generic: sm_80-era) ----------------------
__device__ __forceinline__ uint32_t smem_u32(const void* p) {
    uint32_t a;
    asm("{ .reg .u64 t; cvta.to.shared.u64 t, %1; cvt.u32.u64 %0, t; }" : "=r"(a) : "l"(p));
    return a;
}
__device__ __forceinline__ void cp16(uint32_t saddr, const void* g, int srcsize) {
    asm volatile("cp.async.cg.shared.global [%0], [%1], 16, %2;"
                 :: "r"(saddr), "l"(g), "r"(srcsize) : "memory");
}
#define CP_COMMIT() asm volatile("cp.async.commit_group;" ::: "memory")

#define LDSM_X4(d0, d1, d2, d3, addr) \
    asm volatile("ldmatrix.sync.aligned.m8n8.x4.shared.b16 {%0,%1,%2,%3}, [%4];" \
                 : "=r"(d0), "=r"(d1), "=r"(d2), "=r"(d3) : "r"(addr))

__device__ __forceinline__ void mma16816(float* c, const uint32_t* a, const uint32_t* b) {
    asm volatile(
        "mma.sync.aligned.m16n8k16.row.col.f32.bf16.bf16.f32 "
        "{%0,%1,%2,%3}, {%4,%5,%6,%7}, {%8,%9}, {%0,%1,%2,%3};"
        : "+f"(c[0]), "+f"(c[1]), "+f"(c[2]), "+f"(c[3])
        : "r"(a[0]), "r"(a[1]), "r"(a[2]), "r"(a[3]), "r"(b[0]), "r"(b[1]));
}

// ---------------- precision-split prep --------------------------------------
__global__ void prep_x_kernel(const float* __restrict__ x, int total) {
    int i = blockIdx.x * blockDim.x + threadIdx.x;
    if (i < total) {
        float v = x[i];
        __nv_bfloat16 h = __float2bfloat16(v);
        float r = v - __bfloat162float(h);
        g_xhi[i] = h;
        g_xlo[i] = __float2bfloat16(r);
    }
}
__global__ void prep_bt_kernel(const float* __restrict__ W, const float* __restrict__ skw) {
    int i = blockIdx.x * blockDim.x + threadIdx.x;
    if (i < 512 * 256) {
        int n = i >> 8, k = i & 255;
        float v = (n < 256) ? W[k * 256 + n] : skw[k * 256 + (n - 256)];
        __nv_bfloat16 h = __float2bfloat16(v);
        float r = v - __bfloat162float(h);
        g_bthi[i] = h;
        g_btlo[i] = __float2bfloat16(r);
    }
}

// ---------------- HMMA GEMM: C[M,512] = A[M,256] @ BT^T ----------------------
// hi/lo bf16 error compensation: hi*hi + hi*lo + lo*hi, fp32 accum.
// Block tile 128x128x32, 8 warps (2m x 4n), warp tile 64x32.
// smem: padded rows of 40 bf16 (80 B); per stage: Ahi/Alo (128x32) + Bhi/Blo.
#define LDA_PAD 40
#define ST_AHI  0
#define ST_ALO  10240
#define ST_BHI  20480
#define ST_BLO  30720
#define ST_SIZE 40960
#define GEMM_SMEM (2 * ST_SIZE)

// Each stage tile: 128 rows x 32 k per array (A hi/lo, B hi/lo) = 4 x 8 KB.
// 256 threads: each thread copies 16B from TWO rows (r0 and r0+64) per array.
__device__ __forceinline__ void issue_stage(uint32_t sb, int stage, int k0,
                                            int bm, int bn, int M, int tid) {
    uint32_t base = sb + stage * ST_SIZE;
    int r0   = tid >> 2;              // 0..63
    int c8   = tid & 3;               // 16B chunk within 64B row
    int gcol = k0 + c8 * 8;
#pragma unroll
    for (int half = 0; half < 2; half++) {
        int row = r0 + half * 64;     // 0..127
        uint32_t dst = row * LDA_PAD * 2 + c8 * 16;

        int gr  = bm * 128 + row;
        int okA = (gr < M) ? 16 : 0;
        int grc = (gr < M) ? gr : (M - 1);
        cp16(base + ST_AHI + dst, &g_xhi[(size_t)grc * 256 + gcol], okA);
        cp16(base + ST_ALO + dst, &g_xlo[(size_t)grc * 256 + gcol], okA);

        int gn = bn * 128 + row;
        cp16(base + ST_BHI + dst, &g_bthi[(size_t)gn * 256 + gcol], 16);
        cp16(base + ST_BLO + dst, &g_btlo[(size_t)gn * 256 + gcol], 16);
    }
}

__global__ __launch_bounds__(256, 1) void gemm_kernel(int M)
{
    extern __shared__ __align__(16) char smem[];
    const uint32_t sb = smem_u32(smem);
    const int tid  = threadIdx.x;
    const int wid  = tid >> 5;
    const int lane = tid & 31;
    const int bm   = blockIdx.x;
    const int bn   = blockIdx.y;

    const int wm = (wid >> 2) * 64;   // warp m offset (0 / 64)
    const int wn = (wid & 3) * 32;    // warp n offset (0/32/64/96)

    float acc[4][4][4];
#pragma unroll
    for (int i = 0; i < 4; i++)
#pragma unroll
        for (int j = 0; j < 4; j++)
#pragma unroll
            for (int q = 0; q < 4; q++) acc[i][j][q] = 0.f;

    const int g8 = lane >> 3;    // 0..3 (ldmatrix address group)
    const int r8 = lane & 7;     // 0..7

    issue_stage(sb, 0, 0, bm, bn, M, tid);
    CP_COMMIT();

#pragma unroll 1
    for (int ks = 0; ks < 8; ks++) {
        if (ks < 7) {
            issue_stage(sb, (ks + 1) & 1, (ks + 1) * 32, bm, bn, M, tid);
            CP_COMMIT();
            asm volatile("cp.async.wait_group 1;" ::: "memory");
        } else {
            asm volatile("cp.async.wait_group 0;" ::: "memory");
        }
        __syncthreads();

        const uint32_t st = sb + (ks & 1) * ST_SIZE;
#pragma unroll
        for (int k16 = 0; k16 < 32; k16 += 16) {
            uint32_t ah[4][4], al[4][4], bh[4][2], bl[4][2];
            // A frags: matrices (m0-7,k0)(m8-15,k0)(m0-7,k8)(m8-15,k8)
            {
                int arow = wm + (g8 & 1) * 8 + r8;
                int acol = k16 + (g8 >> 1) * 8;
                uint32_t aoff = (uint32_t)(arow * LDA_PAD + acol) * 2;
#pragma unroll
                for (int mi = 0; mi < 4; mi++) {
                    uint32_t ad = st + aoff + (uint32_t)(mi * 16 * LDA_PAD * 2);
                    LDSM_X4(ah[mi][0], ah[mi][1], ah[mi][2], ah[mi][3], ad + ST_AHI);
                    LDSM_X4(al[mi][0], al[mi][1], al[mi][2], al[mi][3], ad + ST_ALO);
                }
            }
            // B frags: matrices (n0-7,k0)(n0-7,k8)(n8-15,k0)(n8-15,k8)
            {
                int brow = wn + (g8 >> 1) * 8 + r8;
                int bcol = k16 + (g8 & 1) * 8;
                uint32_t boff = (uint32_t)(brow * LDA_PAD + bcol) * 2;
#pragma unroll
                for (int j = 0; j < 2; j++) {
                    uint32_t bd = st + boff + (uint32_t)(j * 16 * LDA_PAD * 2);
                    LDSM_X4(bh[2 * j][0], bh[2 * j][1], bh[2 * j + 1][0], bh[2 * j + 1][1],
                            bd + ST_BHI);
                    LDSM_X4(bl[2 * j][0], bl[2 * j][1], bl[2 * j + 1][0], bl[2 * j + 1][1],
                            bd + ST_BLO);
                }
            }
#pragma unroll
            for (int mi = 0; mi < 4; mi++)
#pragma unroll
                for (int ni = 0; ni < 4; ni++) {
                    mma16816(acc[mi][ni], ah[mi], bh[ni]);
                    mma16816(acc[mi][ni], ah[mi], bl[ni]);
                    mma16816(acc[mi][ni], al[mi], bh[ni]);
                }
        }
        __syncthreads();
    }

    // epilogue: bn 0,1 -> g_proj ; bn 2,3 -> g_skipb
    float* dst = (bn < 2) ? g_proj : g_skipb;
    const int colbase = (bn & 1) * 128 + wn;
#pragma unroll
    for (int mi = 0; mi < 4; mi++) {
        int gr = bm * 128 + wm + mi * 16 + (lane >> 2);
#pragma unroll
        for (int ni = 0; ni < 4; ni++) {
            int gc = colbase + ni * 8 + (lane & 3) * 2;
            if (gr < M)
                *(float2*)&dst[(size_t)gr * 256 + gc] =
                    make_float2(acc[mi][ni][0], acc[mi][ni][1]);
            if (gr + 8 < M)
                *(float2*)&dst[(size_t)(gr + 8) * 256 + gc] =
                    make_float2(acc[mi][ni][2], acc[mi][ni][3]);
        }
    }
}

// ---------------- per-node per-head attention scores ------------------------
__global__ void score_kernel(const float* __restrict__ a_src,
                             const float* __restrict__ a_trg, int Nn)
{
    int w    = (blockIdx.x * blockDim.x + threadIdx.x) >> 5;
    int lane = threadIdx.x & 31;
    if (w >= Nn * NH) return;
    int n = w >> 2, h = w & 3;

    const float* pr = g_proj + (size_t)n * HF + h * NF;
    float p0 = pr[lane], p1 = pr[lane + 32];
    const float* as = a_src + h * NF;
    const float* at = a_trg + h * NF;
    float ss = p0 * as[lane] + p1 * as[lane + 32];
    float st = p0 * at[lane] + p1 * at[lane + 32];
#pragma unroll
    for (int o = 16; o; o >>= 1) {
        ss += __shfl_xor_sync(0xffffffffu, ss, o);
        st += __shfl_xor_sync(0xffffffffu, st, o);
    }
    if (lane == 0) {
        g_ssrc[n * NH + h] = ss;
        g_strg[n * NH + h] = st;
    }
}

// ---------------- CSR construction ------------------------------------------
__global__ void zero_deg_kernel(int Nn)
{
    int i = blockIdx.x * blockDim.x + threadIdx.x;
    if (i < Nn) g_deg[i] = 0;
}
__global__ void hist_kernel(const int* __restrict__ etrg, int E)
{
    int e = blockIdx.x * blockDim.x + threadIdx.x;
    if (e < E) atomicAdd(&g_deg[etrg[e]], 1);
}
__global__ void scan_kernel(int Nn)
{
    __shared__ int sh[1024];
    const int t = threadIdx.x;
    int carry = 0;
    for (int base = 0; base < Nn; base += 1024) {
        int i = base + t;
        int v = (i < Nn) ? g_deg[i] : 0;
        sh[t] = v;
        __syncthreads();
#pragma unroll
        for (int off = 1; off < 1024; off <<= 1) {
            int tv = (t >= off) ? sh[t - off] : 0;
            __syncthreads();
            sh[t] += tv;
            __syncthreads();
        }
        int excl  = sh[t] - v;
        int total = sh[1023];
        if (i < Nn) {
            g_rowstart[i] = carry + excl;
            g_pos[i]      = carry + excl;
        }
        carry += total;
        __syncthreads();
    }
    if (t == 0) g_rowstart[Nn] = carry;
}
__global__ void fill_kernel(const int* __restrict__ esrc,
                            const int* __restrict__ etrg, int E)
{
    int e = blockIdx.x * blockDim.x + threadIdx.x;
    if (e < E) {
        int tnode = etrg[e];
        int p = atomicAdd(&g_pos[tnode], 1);
        g_csr[p] = esrc[e];
    }
}

// ---------------- softmax-weighted aggregation + skip + bias + LeakyReLU ----
__global__ void agg_kernel(const float* __restrict__ bias,
                           float* __restrict__ out, int Nn)
{
    int w    = (blockIdx.x * blockDim.x + threadIdx.x) >> 5;
    int lane = threadIdx.x & 31;
    if (w >= Nn * NH) return;
    int n = w >> 2, h = w & 3;

    int s0 = g_rowstart[n];
    int s1 = g_rowstart[n + 1];
    float strg = g_strg[n * NH + h];

    float denom = 0.f;
    for (int i = s0 + lane; i < s1; i += 32) {
        int s  = g_csr[i];
        float e = g_ssrc[s * NH + h] + strg;
        e = (e > 0.f) ? e : NEG * e;
        denom += __expf(e);
    }
#pragma unroll
    for (int o = 16; o; o >>= 1) denom += __shfl_xor_sync(0xffffffffu, denom, o);
    float inv = 1.f / (denom + 1e-16f);

    float ax = 0.f, ay = 0.f;
    const float* projh = g_proj + h * NF;
    for (int i = s0; i < s1; i++) {
        int s  = g_csr[i];
        float e = g_ssrc[s * NH + h] + strg;
        e = (e > 0.f) ? e : NEG * e;
        float wgt = __expf(e) * inv;
        float2 p = *(const float2*)(projh + (size_t)s * HF + (lane << 1));
        ax += wgt * p.x;
        ay += wgt * p.y;
    }

    size_t off = (size_t)n * HF + h * NF + (lane << 1);
    float2 sk = *(const float2*)(g_skipb + off);
    float bx = bias[h * NF + (lane << 1)];
    float by = bias[h * NF + (lane << 1) + 1];
    float ox = ax + sk.x + bx;
    float oy = ay + sk.y + by;
    ox = (ox > 0.f) ? ox : NEG * ox;
    oy = (oy > 0.f) ? oy : NEG * oy;
    *(float2*)(out + off) = make_float2(ox, oy);
}

// ---------------- launch ----------------------------------------------------
extern "C" void kernel_launch(void* const* d_in, const int* in_sizes, int n_in,
                              void* d_out, int out_size)
{
    const float* x      = (const float*)d_in[0];
    const float* W      = (const float*)d_in[1];
    const float* a_src  = (const float*)d_in[2];
    const float* a_trg  = (const float*)d_in[3];
    const float* skip_w = (const float*)d_in[4];
    const float* bias   = (const float*)d_in[5];
    const int*   esrc   = (const int*)d_in[6];
    const int*   etrg   = (const int*)d_in[7];
    float* out = (float*)d_out;

    const int Nn = in_sizes[0] / HF;   // 50000
    const int E  = in_sizes[6];        // 800000

    cudaFuncSetAttribute(gemm_kernel, cudaFuncAttributeMaxDynamicSharedMemorySize, GEMM_SMEM);

    int total = Nn * HF;
    prep_x_kernel<<<(total + 255) / 256, 256>>>(x, total);
    prep_bt_kernel<<<(512 * 256 + 255) / 256, 256>>>(W, skip_w);

    dim3 ggrid((Nn + 127) / 128, 4);
    gemm_kernel<<<ggrid, 256, GEMM_SMEM>>>(Nn);

    int warps = Nn * NH;
    score_kernel<<<(warps * 32 + 255) / 256, 256>>>(a_src, a_trg, Nn);

    zero_deg_kernel<<<(Nn + 255) / 256, 256>>>(Nn);
    hist_kernel<<<(E + 255) / 256, 256>>>(etrg, E);
    scan_kernel<<<1, 1024>>>(Nn);
    fill_kernel<<<(E + 255) / 256, 256>>>(esrc, etrg, E);

    agg_kernel<<<(warps * 32 + 255) / 256, 256>>>(bias, out, Nn);
}

// round 7
// speedup vs baseline: 2.9965x; 1.3554x over previous
#include <cuda_runtime.h>
#include <cuda_bf16.h>
#include <cstdint>

#define MAX_N 50000
#define MAX_E 800000
#define HF    256
#define NH    4
#define NF    64
#define NEG   0.2f

// ---------------- scratch (device globals; no allocations allowed) ----------
__device__ float g_proj [(size_t)MAX_N * HF];
__device__ float g_skipb[(size_t)MAX_N * HF];
__device__ float g_ssrc [MAX_N * NH];
__device__ float g_strg [MAX_N * NH];
__device__ int   g_deg  [MAX_N];
__device__ int   g_rowstart[MAX_N + 1];
__device__ int   g_pos  [MAX_N];
__device__ int   g_csr  [MAX_E];
__device__ __nv_bfloat16 g_xhi[(size_t)MAX_N * HF];
__device__ __nv_bfloat16 g_xlo[(size_t)MAX_N * HF];
__device__ __nv_bfloat16 g_bthi[512 * 256];   // [n 0..511][k] = (W | skip_w)^T
__device__ __nv_bfloat16 g_btlo[512 * 256];

// ---------------- PTX helpers (arch-generic: sm_80-era) ----------------------
__device__ __forceinline__ uint32_t smem_u32(const void* p) {
    uint32_t a;
    asm("{ .reg .u64 t; cvta.to.shared.u64 t, %1; cvt.u32.u64 %0, t; }" : "=r"(a) : "l"(p));
    return a;
}
__device__ __forceinline__ void cp16(uint32_t saddr, const void* g, int srcsize) {
    asm volatile("cp.async.cg.shared.global [%0], [%1], 16, %2;"
                 :: "r"(saddr), "l"(g), "r"(srcsize) : "memory");
}
#define CP_COMMIT() asm volatile("cp.async.commit_group;" ::: "memory")

#define LDSM_X4(d0, d1, d2, d3, addr) \
    asm volatile("ldmatrix.sync.aligned.m8n8.x4.shared.b16 {%0,%1,%2,%3}, [%4];" \
                 : "=r"(d0), "=r"(d1), "=r"(d2), "=r"(d3) : "r"(addr))

__device__ __forceinline__ void mma16816(float* c, const uint32_t* a, const uint32_t* b) {
    asm volatile(
        "mma.sync.aligned.m16n8k16.row.col.f32.bf16.bf16.f32 "
        "{%0,%1,%2,%3}, {%4,%5,%6,%7}, {%8,%9}, {%0,%1,%2,%3};"
        : "+f"(c[0]), "+f"(c[1]), "+f"(c[2]), "+f"(c[3])
        : "r"(a[0]), "r"(a[1]), "r"(a[2]), "r"(a[3]), "r"(b[0]), "r"(b[1]));
}

// ---------------- precision-split prep --------------------------------------
__global__ void prep_x_kernel(const float4* __restrict__ x4, int total4) {
    int i = blockIdx.x * blockDim.x + threadIdx.x;
    if (i < total4) {
        float4 v = x4[i];
        __nv_bfloat16 hx = __float2bfloat16(v.x), hy = __float2bfloat16(v.y);
        __nv_bfloat16 hz = __float2bfloat16(v.z), hw = __float2bfloat16(v.w);
        __nv_bfloat162* hi2 = (__nv_bfloat162*)g_xhi;
        __nv_bfloat162* lo2 = (__nv_bfloat162*)g_xlo;
        hi2[i * 2 + 0] = __nv_bfloat162(hx, hy);
        hi2[i * 2 + 1] = __nv_bfloat162(hz, hw);
        lo2[i * 2 + 0] = __nv_bfloat162(__float2bfloat16(v.x - __bfloat162float(hx)),
                                        __float2bfloat16(v.y - __bfloat162float(hy)));
        lo2[i * 2 + 1] = __nv_bfloat162(__float2bfloat16(v.z - __bfloat162float(hz)),
                                        __float2bfloat16(v.w - __bfloat162float(hw)));
    }
}
// also zeroes g_deg (saves one launch)
__global__ void prep_bt_kernel(const float* __restrict__ W, const float* __restrict__ skw,
                               int Nn) {
    int i = blockIdx.x * blockDim.x + threadIdx.x;
    if (i < Nn) g_deg[i] = 0;
    if (i < 512 * 256) {
        int n = i >> 8, k = i & 255;
        float v = (n < 256) ? W[k * 256 + n] : skw[k * 256 + (n - 256)];
        __nv_bfloat16 h = __float2bfloat16(v);
        float r = v - __bfloat162float(h);
        g_bthi[i] = h;
        g_btlo[i] = __float2bfloat16(r);
    }
}

// ---------------- HMMA GEMM: C[M,512] = A[M,256] @ BT^T ----------------------
// hi/lo bf16 error compensation: hi*hi + hi*lo + lo*hi, fp32 accum.
// A-resident: one CTA owns 128 rows, full K=256 in smem; loops 4 bn tiles of
// 128 cols each, streaming B through a 2-stage cp.async pipeline.
#define AP       264      // padded A row stride (elements): 528B -> 4-bank rotation
#define SA_HI    0
#define SA_LO    67584
#define SB_BASE  135168
#define SB_HI    0
#define SB_LO    10240
#define SB_STAGE 20480
#define LDB_PAD  40
#define GEMM_SMEM (135168 + 2 * 20480)   // 176128

__device__ __forceinline__ void issue_A(uint32_t sb, int bm, int M, int tid) {
#pragma unroll
    for (int it = 0; it < 16; it++) {
        int id = tid + it * 256;          // 0..4095
        int r = id >> 5, c = id & 31;     // row, 16B chunk (8 elems)
        int gr = bm * 128 + r;
        int ok = (gr < M) ? 16 : 0;
        int grc = (gr < M) ? gr : (M - 1);
        uint32_t dst = (uint32_t)(r * AP * 2 + c * 16);
        cp16(sb + SA_HI + dst, &g_xhi[(size_t)grc * 256 + c * 8], ok);
        cp16(sb + SA_LO + dst, &g_xlo[(size_t)grc * 256 + c * 8], ok);
    }
}
__device__ __forceinline__ void issue_B(uint32_t sb, int g, int tid) {
    int bn = g >> 3, ks = g & 7;
    uint32_t base = sb + SB_BASE + (uint32_t)(g & 1) * SB_STAGE;
    int r0 = tid >> 2, c8 = tid & 3;
    int gcol = ks * 32 + c8 * 8;
#pragma unroll
    for (int half = 0; half < 2; half++) {
        int row = r0 + half * 64;
        int gn  = bn * 128 + row;
        uint32_t dst = (uint32_t)(row * LDB_PAD * 2 + c8 * 16);
        cp16(base + SB_HI + dst, &g_bthi[(size_t)gn * 256 + gcol], 16);
        cp16(base + SB_LO + dst, &g_btlo[(size_t)gn * 256 + gcol], 16);
    }
}

__global__ __launch_bounds__(256, 1) void gemm_kernel(int M)
{
    extern __shared__ __align__(16) char smem[];
    const uint32_t sb = smem_u32(smem);
    const int tid  = threadIdx.x;
    const int wid  = tid >> 5;
    const int lane = tid & 31;
    const int bm   = blockIdx.x;

    const int wm = (wid >> 2) * 64;   // warp m offset (0 / 64)
    const int wn = (wid & 3) * 32;    // warp n offset (0/32/64/96)

    float acc[4][4][4];
#pragma unroll
    for (int i = 0; i < 4; i++)
#pragma unroll
        for (int j = 0; j < 4; j++)
#pragma unroll
            for (int q = 0; q < 4; q++) acc[i][j][q] = 0.f;

    const int g8 = lane >> 3;    // ldmatrix address group 0..3
    const int r8 = lane & 7;

    issue_A(sb, bm, M, tid);
    issue_B(sb, 0, tid);
    CP_COMMIT();

#pragma unroll 1
    for (int g = 0; g < 32; g++) {
        if (g < 31) {
            issue_B(sb, g + 1, tid);
            CP_COMMIT();
            asm volatile("cp.async.wait_group 1;" ::: "memory");
        } else {
            asm volatile("cp.async.wait_group 0;" ::: "memory");
        }
        __syncthreads();

        const int bn = g >> 3, ks = g & 7;
        const uint32_t stB = sb + SB_BASE + (uint32_t)(g & 1) * SB_STAGE;
#pragma unroll
        for (int k16 = 0; k16 < 32; k16 += 16) {
            uint32_t ah[4][4], al[4][4], bh[4][2], bl[4][2];
            // A frags from resident tile
            {
                int arow = wm + (g8 & 1) * 8 + r8;
                int acol = ks * 32 + k16 + (g8 >> 1) * 8;
                uint32_t aoff = (uint32_t)(arow * AP + acol) * 2;
#pragma unroll
                for (int mi = 0; mi < 4; mi++) {
                    uint32_t ad = sb + aoff + (uint32_t)(mi * 16 * AP * 2);
                    LDSM_X4(ah[mi][0], ah[mi][1], ah[mi][2], ah[mi][3], ad + SA_HI);
                    LDSM_X4(al[mi][0], al[mi][1], al[mi][2], al[mi][3], ad + SA_LO);
                }
            }
            // B frags from stage buffer
            {
                int brow = wn + (g8 >> 1) * 8 + r8;
                int bcol = k16 + (g8 & 1) * 8;
                uint32_t boff = (uint32_t)(brow * LDB_PAD + bcol) * 2;
#pragma unroll
                for (int j = 0; j < 2; j++) {
                    uint32_t bd = stB + boff + (uint32_t)(j * 16 * LDB_PAD * 2);
                    LDSM_X4(bh[2 * j][0], bh[2 * j][1], bh[2 * j + 1][0], bh[2 * j + 1][1],
                            bd + SB_HI);
                    LDSM_X4(bl[2 * j][0], bl[2 * j][1], bl[2 * j + 1][0], bl[2 * j + 1][1],
                            bd + SB_LO);
                }
            }
#pragma unroll
            for (int mi = 0; mi < 4; mi++)
#pragma unroll
                for (int ni = 0; ni < 4; ni++) {
                    mma16816(acc[mi][ni], ah[mi], bh[ni]);
                    mma16816(acc[mi][ni], ah[mi], bl[ni]);
                    mma16816(acc[mi][ni], al[mi], bh[ni]);
                }
        }
        __syncthreads();

        if (ks == 7) {
            // epilogue for this bn: bn 0,1 -> g_proj ; bn 2,3 -> g_skipb
            float* dst = (bn < 2) ? g_proj : g_skipb;
            const int colbase = (bn & 1) * 128 + wn;
#pragma unroll
            for (int mi = 0; mi < 4; mi++) {
                int gr = bm * 128 + wm + mi * 16 + (lane >> 2);
#pragma unroll
                for (int ni = 0; ni < 4; ni++) {
                    int gc = colbase + ni * 8 + (lane & 3) * 2;
                    if (gr < M)
                        *(float2*)&dst[(size_t)gr * 256 + gc] =
                            make_float2(acc[mi][ni][0], acc[mi][ni][1]);
                    if (gr + 8 < M)
                        *(float2*)&dst[(size_t)(gr + 8) * 256 + gc] =
                            make_float2(acc[mi][ni][2], acc[mi][ni][3]);
                    acc[mi][ni][0] = acc[mi][ni][1] = acc[mi][ni][2] = acc[mi][ni][3] = 0.f;
                }
            }
        }
    }
}

// ---------------- attention scores: one warp per node, 4 heads --------------
__global__ void score_kernel(const float* __restrict__ a_src,
                             const float* __restrict__ a_trg, int Nn)
{
    int w    = (blockIdx.x * blockDim.x + threadIdx.x) >> 5;
    int lane = threadIdx.x & 31;
    if (w >= Nn) return;
    int h = lane >> 3, q = lane & 7;

    const float* pr = g_proj + (size_t)w * HF + lane * 8;
    float4 p0 = *(const float4*)pr;
    float4 p1 = *(const float4*)(pr + 4);
    float4 s0 = *(const float4*)(a_src + lane * 8);
    float4 s1 = *(const float4*)(a_src + lane * 8 + 4);
    float4 t0 = *(const float4*)(a_trg + lane * 8);
    float4 t1 = *(const float4*)(a_trg + lane * 8 + 4);

    float ss = p0.x * s0.x + p0.y * s0.y + p0.z * s0.z + p0.w * s0.w
             + p1.x * s1.x + p1.y * s1.y + p1.z * s1.z + p1.w * s1.w;
    float st = p0.x * t0.x + p0.y * t0.y + p0.z * t0.z + p0.w * t0.w
             + p1.x * t1.x + p1.y * t1.y + p1.z * t1.z + p1.w * t1.w;
#pragma unroll
    for (int o = 4; o; o >>= 1) {
        ss += __shfl_xor_sync(0xffffffffu, ss, o);
        st += __shfl_xor_sync(0xffffffffu, st, o);
    }
    if (q == 0) {
        g_ssrc[w * NH + h] = ss;
        g_strg[w * NH + h] = st;
    }
}

// ---------------- CSR construction ------------------------------------------
__global__ void hist_kernel(const int* __restrict__ etrg, int E)
{
    int e = blockIdx.x * blockDim.x + threadIdx.x;
    if (e < E) atomicAdd(&g_deg[etrg[e]], 1);
}
// single block, 1024 threads, 4 elems/thread, shfl-based scan
__global__ void scan_kernel(int Nn)
{
    __shared__ int warpsum[32];
    __shared__ int s_carry;
    const int t = threadIdx.x, lane = t & 31, wid = t >> 5;
    if (t == 0) s_carry = 0;
    __syncthreads();
    for (int base = 0; base < Nn; base += 4096) {
        int i0 = base + t * 4;
        int v[4];
#pragma unroll
        for (int j = 0; j < 4; j++) v[j] = (i0 + j < Nn) ? g_deg[i0 + j] : 0;
        int tsum = v[0] + v[1] + v[2] + v[3];
        int x = tsum;
#pragma unroll
        for (int o = 1; o < 32; o <<= 1) {
            int y = __shfl_up_sync(0xffffffffu, x, o);
            if (lane >= o) x += y;
        }
        if (lane == 31) warpsum[wid] = x;
        __syncthreads();
        if (wid == 0) {
            int wv = warpsum[lane];
            int xx = wv;
#pragma unroll
            for (int o = 1; o < 32; o <<= 1) {
                int y = __shfl_up_sync(0xffffffffu, xx, o);
                if (lane >= o) xx += y;
            }
            warpsum[lane] = xx - wv;
        }
        __syncthreads();
        int run = s_carry + warpsum[wid] + (x - tsum);
#pragma unroll
        for (int j = 0; j < 4; j++) {
            if (i0 + j < Nn) { g_rowstart[i0 + j] = run; g_pos[i0 + j] = run; }
            run += v[j];
        }
        __syncthreads();
        if (t == 1023) s_carry = run;
        __syncthreads();
    }
    if (t == 0) g_rowstart[Nn] = s_carry;
}
__global__ void fill_kernel(const int* __restrict__ esrc,
                            const int* __restrict__ etrg, int E)
{
    int e = blockIdx.x * blockDim.x + threadIdx.x;
    if (e < E) {
        int tnode = etrg[e];
        int p = atomicAdd(&g_pos[tnode], 1);
        g_csr[p] = esrc[e];
    }
}

// ---------------- aggregation: one warp per node, all 4 heads ----------------
__global__ void agg_kernel(const float* __restrict__ bias,
                           float* __restrict__ out, int Nn)
{
    int w    = (blockIdx.x * blockDim.x + threadIdx.x) >> 5;
    int lane = threadIdx.x & 31;
    if (w >= Nn) return;
    const int h = lane >> 3, q = lane & 7;

    const int s0 = g_rowstart[w];
    const int s1 = g_rowstart[w + 1];
    const float strg = g_strg[w * NH + h];

    // pass 1: 4 head denominators in parallel (lane handles edges q mod 8 for head h)
    float denom = 0.f;
    for (int i = s0 + q; i < s1; i += 8) {
        int s  = g_csr[i];
        float e = g_ssrc[s * NH + h] + strg;
        e = (e > 0.f) ? e : NEG * e;
        denom += __expf(e);
    }
    denom += __shfl_xor_sync(0xffffffffu, denom, 4);
    denom += __shfl_xor_sync(0xffffffffu, denom, 2);
    denom += __shfl_xor_sync(0xffffffffu, denom, 1);
    const float inv = 1.f / (denom + 1e-16f);

    // pass 2: full 256-feature gather per edge (lane covers cols lane*8..+7 of head h)
    float a0 = 0.f, a1 = 0.f, a2 = 0.f, a3 = 0.f, a4 = 0.f, a5 = 0.f, a6 = 0.f, a7 = 0.f;
    for (int i = s0; i < s1; i++) {
        int s  = g_csr[i];
        float e = g_ssrc[s * NH + h] + strg;
        e = (e > 0.f) ? e : NEG * e;
        float wgt = __expf(e) * inv;
        const float* pr = g_proj + (size_t)s * HF + lane * 8;
        float4 p0 = *(const float4*)pr;
        float4 p1 = *(const float4*)(pr + 4);
        a0 += wgt * p0.x; a1 += wgt * p0.y; a2 += wgt * p0.z; a3 += wgt * p0.w;
        a4 += wgt * p1.x; a5 += wgt * p1.y; a6 += wgt * p1.z; a7 += wgt * p1.w;
    }

    const size_t off = (size_t)w * HF + lane * 8;
    float4 k0 = *(const float4*)&g_skipb[off];
    float4 k1 = *(const float4*)&g_skipb[off + 4];
    float4 b0 = *(const float4*)&bias[lane * 8];
    float4 b1 = *(const float4*)&bias[lane * 8 + 4];
    float o0 = a0 + k0.x + b0.x, o1 = a1 + k0.y + b0.y;
    float o2 = a2 + k0.z + b0.z, o3 = a3 + k0.w + b0.w;
    float o4 = a4 + k1.x + b1.x, o5 = a5 + k1.y + b1.y;
    float o6 = a6 + k1.z + b1.z, o7 = a7 + k1.w + b1.w;
    o0 = (o0 > 0.f) ? o0 : NEG * o0;  o1 = (o1 > 0.f) ? o1 : NEG * o1;
    o2 = (o2 > 0.f) ? o2 : NEG * o2;  o3 = (o3 > 0.f) ? o3 : NEG * o3;
    o4 = (o4 > 0.f) ? o4 : NEG * o4;  o5 = (o5 > 0.f) ? o5 : NEG * o5;
    o6 = (o6 > 0.f) ? o6 : NEG * o6;  o7 = (o7 > 0.f) ? o7 : NEG * o7;
    *(float4*)&out[off]     = make_float4(o0, o1, o2, o3);
    *(float4*)&out[off + 4] = make_float4(o4, o5, o6, o7);
}

// ---------------- launch ----------------------------------------------------
extern "C" void kernel_launch(void* const* d_in, const int* in_sizes, int n_in,
                              void* d_out, int out_size)
{
    const float* x      = (const float*)d_in[0];
    const float* W      = (const float*)d_in[1];
    const float* a_src  = (const float*)d_in[2];
    const float* a_trg  = (const float*)d_in[3];
    const float* skip_w = (const float*)d_in[4];
    const float* bias   = (const float*)d_in[5];
    const int*   esrc   = (const int*)d_in[6];
    const int*   etrg   = (const int*)d_in[7];
    float* out = (float*)d_out;

    const int Nn = in_sizes[0] / HF;   // 50000
    const int E  = in_sizes[6];        // 800000

    cudaFuncSetAttribute(gemm_kernel, cudaFuncAttributeMaxDynamicSharedMemorySize, GEMM_SMEM);

    int total4 = Nn * HF / 4;
    prep_x_kernel<<<(total4 + 255) / 256, 256>>>((const float4*)x, total4);
    prep_bt_kernel<<<(512 * 256 + 255) / 256, 256>>>(W, skip_w, Nn);

    gemm_kernel<<<(Nn + 127) / 128, 256, GEMM_SMEM>>>(Nn);

    int nblk = (Nn * 32 + 255) / 256;
    score_kernel<<<nblk, 256>>>(a_src, a_trg, Nn);

    hist_kernel<<<(E + 255) / 256, 256>>>(etrg, E);
    scan_kernel<<<1, 1024>>>(Nn);
    fill_kernel<<<(E + 255) / 256, 256>>>(esrc, etrg, E);

    agg_kernel<<<nblk, 256>>>(bias, out, Nn);
}

// round 8
// speedup vs baseline: 3.1694x; 1.0577x over previous
#include <cuda_runtime.h>
#include <cuda_bf16.h>
#include <cstdint>

#define MAX_N 50000
#define MAX_E 800000
#define HF    256
#define NH    4
#define NF    64
#define NEG   0.2f

// ---------------- scratch (device globals; no allocations allowed) ----------
__device__ float g_proj [(size_t)MAX_N * HF];
__device__ float g_skipb[(size_t)MAX_N * HF];
__device__ float g_ssrc [MAX_N * NH];
__device__ float g_strg [MAX_N * NH];
__device__ int   g_deg  [MAX_N];
__device__ int   g_rowstart[MAX_N + 1];
__device__ int   g_pos  [MAX_N];
__device__ int   g_csr  [MAX_E];
__device__ __nv_bfloat16 g_bthi[512 * 256];   // [n 0..511][k] = (W | skip_w)^T
__device__ __nv_bfloat16 g_btlo[512 * 256];

// ---------------- PTX helpers (arch-generic: sm_80-era) ----------------------
__device__ __forceinline__ uint32_t smem_u32(const void* p) {
    uint32_t a;
    asm("{ .reg .u64 t; cvta.to.shared.u64 t, %1; cvt.u32.u64 %0, t; }" : "=r"(a) : "l"(p));
    return a;
}
__device__ __forceinline__ void cp16(uint32_t saddr, const void* g, int srcsize) {
    asm volatile("cp.async.cg.shared.global [%0], [%1], 16, %2;"
                 :: "r"(saddr), "l"(g), "r"(srcsize) : "memory");
}
#define CP_COMMIT() asm volatile("cp.async.commit_group;" ::: "memory")

#define LDSM_X4(d0, d1, d2, d3, addr) \
    asm volatile("ldmatrix.sync.aligned.m8n8.x4.shared.b16 {%0,%1,%2,%3}, [%4];" \
                 : "=r"(d0), "=r"(d1), "=r"(d2), "=r"(d3) : "r"(addr))

__device__ __forceinline__ void mma16816(float* c, const uint32_t* a, const uint32_t* b) {
    asm volatile(
        "mma.sync.aligned.m16n8k16.row.col.f32.bf16.bf16.f32 "
        "{%0,%1,%2,%3}, {%4,%5,%6,%7}, {%8,%9}, {%0,%1,%2,%3};"
        : "+f"(c[0]), "+f"(c[1]), "+f"(c[2]), "+f"(c[3])
        : "r"(a[0]), "r"(a[1]), "r"(a[2]), "r"(a[3]), "r"(b[0]), "r"(b[1]));
}

// ---------------- weight prep (also zeroes g_deg) -----------------------------
__global__ void prep_bt_kernel(const float* __restrict__ W, const float* __restrict__ skw,
                               int Nn) {
    int i = blockIdx.x * blockDim.x + threadIdx.x;
    if (i < Nn) g_deg[i] = 0;
    if (i < 512 * 256) {
        int n = i >> 8, k = i & 255;
        float v = (n < 256) ? W[k * 256 + n] : skw[k * 256 + (n - 256)];
        __nv_bfloat16 h = __float2bfloat16(v);
        float r = v - __bfloat162float(h);
        g_bthi[i] = h;
        g_btlo[i] = __float2bfloat16(r);
    }
}

// ---------------- HMMA GEMM: C[M,512] = A[M,256] @ BT^T ----------------------
// hi/lo bf16 error compensation: hi*hi + hi*lo + lo*hi, fp32 accum.
// A-resident: one CTA owns 128 rows, full K=256 in smem (converted in-kernel
// from fp32 x); loops 4 bn tiles of 128 cols, streaming B via 2-stage cp.async.
#define AP       264      // padded A row stride (elements)
#define SA_HI    0
#define SA_LO    67584
#define SB_BASE  135168
#define SB_HI    0
#define SB_LO    10240
#define SB_STAGE 20480
#define LDB_PAD  40
#define GEMM_SMEM (135168 + 2 * 20480)   // 176128

__device__ __forceinline__ void load_A_convert(char* smem, const float* __restrict__ x,
                                               int bm, int M, int tid) {
#pragma unroll
    for (int it = 0; it < 16; it++) {
        int id = tid + it * 256;          // 0..4095 : 128 rows x 32 chunks(8 floats)
        int r = id >> 5, c = id & 31;
        int gr = bm * 128 + r;
        float4 v0 = make_float4(0.f, 0.f, 0.f, 0.f), v1 = v0;
        if (gr < M) {
            const float* src = x + (size_t)gr * 256 + c * 8;
            v0 = *(const float4*)src;
            v1 = *(const float4*)(src + 4);
        }
        float f[8] = {v0.x, v0.y, v0.z, v0.w, v1.x, v1.y, v1.z, v1.w};
        __nv_bfloat162 hi2[4], lo2[4];
#pragma unroll
        for (int j = 0; j < 4; j++) {
            __nv_bfloat16 ha = __float2bfloat16(f[2 * j]);
            __nv_bfloat16 hb = __float2bfloat16(f[2 * j + 1]);
            hi2[j] = __nv_bfloat162(ha, hb);
            lo2[j] = __nv_bfloat162(__float2bfloat16(f[2 * j]     - __bfloat162float(ha)),
                                    __float2bfloat16(f[2 * j + 1] - __bfloat162float(hb)));
        }
        uint32_t dst = (uint32_t)(r * AP * 2 + c * 16);
        *(uint4*)(smem + SA_HI + dst) = *(uint4*)hi2;
        *(uint4*)(smem + SA_LO + dst) = *(uint4*)lo2;
    }
}
__device__ __forceinline__ void issue_B(uint32_t sb, int g, int tid) {
    int bn = g >> 3, ks = g & 7;
    uint32_t base = sb + SB_BASE + (uint32_t)(g & 1) * SB_STAGE;
    int r0 = tid >> 2, c8 = tid & 3;
    int gcol = ks * 32 + c8 * 8;
#pragma unroll
    for (int half = 0; half < 2; half++) {
        int row = r0 + half * 64;
        int gn  = bn * 128 + row;
        uint32_t dst = (uint32_t)(row * LDB_PAD * 2 + c8 * 16);
        cp16(base + SB_HI + dst, &g_bthi[(size_t)gn * 256 + gcol], 16);
        cp16(base + SB_LO + dst, &g_btlo[(size_t)gn * 256 + gcol], 16);
    }
}

__global__ __launch_bounds__(256, 1) void gemm_kernel(const float* __restrict__ x, int M)
{
    extern __shared__ __align__(16) char smem[];
    const uint32_t sb = smem_u32(smem);
    const int tid  = threadIdx.x;
    const int wid  = tid >> 5;
    const int lane = tid & 31;
    const int bm   = blockIdx.x;

    const int wm = (wid >> 2) * 64;   // warp m offset (0 / 64)
    const int wn = (wid & 3) * 32;    // warp n offset (0/32/64/96)

    float acc[4][4][4];
#pragma unroll
    for (int i = 0; i < 4; i++)
#pragma unroll
        for (int j = 0; j < 4; j++)
#pragma unroll
            for (int q = 0; q < 4; q++) acc[i][j][q] = 0.f;

    const int g8 = lane >> 3;    // ldmatrix address group 0..3
    const int r8 = lane & 7;

    issue_B(sb, 0, tid);
    CP_COMMIT();
    load_A_convert(smem, x, bm, M, tid);

#pragma unroll 1
    for (int g = 0; g < 32; g++) {
        if (g < 31) {
            issue_B(sb, g + 1, tid);
            CP_COMMIT();
            asm volatile("cp.async.wait_group 1;" ::: "memory");
        } else {
            asm volatile("cp.async.wait_group 0;" ::: "memory");
        }
        __syncthreads();

        const int bn = g >> 3, ks = g & 7;
        const uint32_t stB = sb + SB_BASE + (uint32_t)(g & 1) * SB_STAGE;
#pragma unroll
        for (int k16 = 0; k16 < 32; k16 += 16) {
            uint32_t ah[4][4], al[4][4], bh[4][2], bl[4][2];
            // A frags from resident tile
            {
                int arow = wm + (g8 & 1) * 8 + r8;
                int acol = ks * 32 + k16 + (g8 >> 1) * 8;
                uint32_t aoff = (uint32_t)(arow * AP + acol) * 2;
#pragma unroll
                for (int mi = 0; mi < 4; mi++) {
                    uint32_t ad = sb + aoff + (uint32_t)(mi * 16 * AP * 2);
                    LDSM_X4(ah[mi][0], ah[mi][1], ah[mi][2], ah[mi][3], ad + SA_HI);
                    LDSM_X4(al[mi][0], al[mi][1], al[mi][2], al[mi][3], ad + SA_LO);
                }
            }
            // B frags from stage buffer
            {
                int brow = wn + (g8 >> 1) * 8 + r8;
                int bcol = k16 + (g8 & 1) * 8;
                uint32_t boff = (uint32_t)(brow * LDB_PAD + bcol) * 2;
#pragma unroll
                for (int j = 0; j < 2; j++) {
                    uint32_t bd = stB + boff + (uint32_t)(j * 16 * LDB_PAD * 2);
                    LDSM_X4(bh[2 * j][0], bh[2 * j][1], bh[2 * j + 1][0], bh[2 * j + 1][1],
                            bd + SB_HI);
                    LDSM_X4(bl[2 * j][0], bl[2 * j][1], bl[2 * j + 1][0], bl[2 * j + 1][1],
                            bd + SB_LO);
                }
            }
#pragma unroll
            for (int mi = 0; mi < 4; mi++)
#pragma unroll
                for (int ni = 0; ni < 4; ni++) {
                    mma16816(acc[mi][ni], ah[mi], bh[ni]);
                    mma16816(acc[mi][ni], ah[mi], bl[ni]);
                    mma16816(acc[mi][ni], al[mi], bh[ni]);
                }
        }
        __syncthreads();

        if (ks == 7) {
            float* dst = (bn < 2) ? g_proj : g_skipb;
            const int colbase = (bn & 1) * 128 + wn;
#pragma unroll
            for (int mi = 0; mi < 4; mi++) {
                int gr = bm * 128 + wm + mi * 16 + (lane >> 2);
#pragma unroll
                for (int ni = 0; ni < 4; ni++) {
                    int gc = colbase + ni * 8 + (lane & 3) * 2;
                    if (gr < M)
                        *(float2*)&dst[(size_t)gr * 256 + gc] =
                            make_float2(acc[mi][ni][0], acc[mi][ni][1]);
                    if (gr + 8 < M)
                        *(float2*)&dst[(size_t)(gr + 8) * 256 + gc] =
                            make_float2(acc[mi][ni][2], acc[mi][ni][3]);
                    acc[mi][ni][0] = acc[mi][ni][1] = acc[mi][ni][2] = acc[mi][ni][3] = 0.f;
                }
            }
        }
    }
}

// ---------------- attention scores: one warp per node, 4 heads --------------
__global__ void score_kernel(const float* __restrict__ a_src,
                             const float* __restrict__ a_trg, int Nn)
{
    int w    = (blockIdx.x * blockDim.x + threadIdx.x) >> 5;
    int lane = threadIdx.x & 31;
    if (w >= Nn) return;
    int h = lane >> 3, q = lane & 7;

    const float* pr = g_proj + (size_t)w * HF + lane * 8;
    float4 p0 = *(const float4*)pr;
    float4 p1 = *(const float4*)(pr + 4);
    float4 s0 = *(const float4*)(a_src + lane * 8);
    float4 s1 = *(const float4*)(a_src + lane * 8 + 4);
    float4 t0 = *(const float4*)(a_trg + lane * 8);
    float4 t1 = *(const float4*)(a_trg + lane * 8 + 4);

    float ss = p0.x * s0.x + p0.y * s0.y + p0.z * s0.z + p0.w * s0.w
             + p1.x * s1.x + p1.y * s1.y + p1.z * s1.z + p1.w * s1.w;
    float st = p0.x * t0.x + p0.y * t0.y + p0.z * t0.z + p0.w * t0.w
             + p1.x * t1.x + p1.y * t1.y + p1.z * t1.z + p1.w * t1.w;
#pragma unroll
    for (int o = 4; o; o >>= 1) {
        ss += __shfl_xor_sync(0xffffffffu, ss, o);
        st += __shfl_xor_sync(0xffffffffu, st, o);
    }
    if (q == 0) {
        g_ssrc[w * NH + h] = ss;
        g_strg[w * NH + h] = st;
    }
}

// ---------------- CSR construction ------------------------------------------
__global__ void hist_kernel(const int* __restrict__ etrg, int E)
{
    int e = blockIdx.x * blockDim.x + threadIdx.x;
    if (e < E) atomicAdd(&g_deg[etrg[e]], 1);
}
__global__ void scan_kernel(int Nn)
{
    __shared__ int warpsum[32];
    __shared__ int s_carry;
    const int t = threadIdx.x, lane = t & 31, wid = t >> 5;
    if (t == 0) s_carry = 0;
    __syncthreads();
    for (int base = 0; base < Nn; base += 4096) {
        int i0 = base + t * 4;
        int v[4];
#pragma unroll
        for (int j = 0; j < 4; j++) v[j] = (i0 + j < Nn) ? g_deg[i0 + j] : 0;
        int tsum = v[0] + v[1] + v[2] + v[3];
        int x = tsum;
#pragma unroll
        for (int o = 1; o < 32; o <<= 1) {
            int y = __shfl_up_sync(0xffffffffu, x, o);
            if (lane >= o) x += y;
        }
        if (lane == 31) warpsum[wid] = x;
        __syncthreads();
        if (wid == 0) {
            int wv = warpsum[lane];
            int xx = wv;
#pragma unroll
            for (int o = 1; o < 32; o <<= 1) {
                int y = __shfl_up_sync(0xffffffffu, xx, o);
                if (lane >= o) xx += y;
            }
            warpsum[lane] = xx - wv;
        }
        __syncthreads();
        int run = s_carry + warpsum[wid] + (x - tsum);
#pragma unroll
        for (int j = 0; j < 4; j++) {
            if (i0 + j < Nn) { g_rowstart[i0 + j] = run; g_pos[i0 + j] = run; }
            run += v[j];
        }
        __syncthreads();
        if (t == 1023) s_carry = run;
        __syncthreads();
    }
    if (t == 0) g_rowstart[Nn] = s_carry;
}
__global__ void fill_kernel(const int* __restrict__ esrc,
                            const int* __restrict__ etrg, int E)
{
    int e = blockIdx.x * blockDim.x + threadIdx.x;
    if (e < E) {
        int tnode = etrg[e];
        int p = atomicAdd(&g_pos[tnode], 1);
        g_csr[p] = esrc[e];
    }
}

// ---------------- aggregation: single pass, owner-computed weights ----------
// out_n = (sum_i e_i * proj_src_i) / (sum_i e_i)  -- normalize once at the end.
// Per 8-edge batch, lane (h,q) computes exp for edge q (head h); others get
// weight + src idx via shfl. expf count: 4 per edge instead of 32.
__global__ void agg_kernel(const float* __restrict__ bias,
                           float* __restrict__ out, int Nn)
{
    int w    = (blockIdx.x * blockDim.x + threadIdx.x) >> 5;
    int lane = threadIdx.x & 31;
    if (w >= Nn) return;
    const int h = lane >> 3, q = lane & 7;
    const int hb = h << 3;

    const int s0 = g_rowstart[w];
    const int s1 = g_rowstart[w + 1];
    const float strg = g_strg[w * NH + h];

    float denom = 0.f;
    float a0 = 0.f, a1 = 0.f, a2 = 0.f, a3 = 0.f, a4 = 0.f, a5 = 0.f, a6 = 0.f, a7 = 0.f;

    int i = s0;
    for (; i + 8 <= s1; i += 8) {
        int   sq = g_csr[i + q];
        float e  = g_ssrc[sq * NH + h] + strg;
        e = (e > 0.f) ? e : NEG * e;
        float wq = __expf(e);
        denom += wq;
#pragma unroll
        for (int j = 0; j < 8; j++) {
            float wgt = __shfl_sync(0xffffffffu, wq, hb + j);
            int   s   = __shfl_sync(0xffffffffu, sq, j);       // heads share src
            const float* pr = g_proj + (size_t)s * HF + lane * 8;
            float4 p0 = *(const float4*)pr;
            float4 p1 = *(const float4*)(pr + 4);
            a0 += wgt * p0.x; a1 += wgt * p0.y; a2 += wgt * p0.z; a3 += wgt * p0.w;
            a4 += wgt * p1.x; a5 += wgt * p1.y; a6 += wgt * p1.z; a7 += wgt * p1.w;
        }
    }
    if (i < s1) {
        int nb = s1 - i;
        float wq = 0.f;
        int   sq = 0;
        if (q < nb) {
            sq = g_csr[i + q];
            float e = g_ssrc[sq * NH + h] + strg;
            e = (e > 0.f) ? e : NEG * e;
            wq = __expf(e);
        }
        denom += wq;
        for (int j = 0; j < nb; j++) {
            float wgt = __shfl_sync(0xffffffffu, wq, hb + j);
            int   s   = __shfl_sync(0xffffffffu, sq, j);
            const float* pr = g_proj + (size_t)s * HF + lane * 8;
            float4 p0 = *(const float4*)pr;
            float4 p1 = *(const float4*)(pr + 4);
            a0 += wgt * p0.x; a1 += wgt * p0.y; a2 += wgt * p0.z; a3 += wgt * p0.w;
            a4 += wgt * p1.x; a5 += wgt * p1.y; a6 += wgt * p1.z; a7 += wgt * p1.w;
        }
    }

    denom += __shfl_xor_sync(0xffffffffu, denom, 4);
    denom += __shfl_xor_sync(0xffffffffu, denom, 2);
    denom += __shfl_xor_sync(0xffffffffu, denom, 1);
    const float inv = 1.f / (denom + 1e-16f);

    const size_t off = (size_t)w * HF + lane * 8;
    float4 k0 = *(const float4*)&g_skipb[off];
    float4 k1 = *(const float4*)&g_skipb[off + 4];
    float4 b0 = *(const float4*)&bias[lane * 8];
    float4 b1 = *(const float4*)&bias[lane * 8 + 4];
    float o0 = a0 * inv + k0.x + b0.x, o1 = a1 * inv + k0.y + b0.y;
    float o2 = a2 * inv + k0.z + b0.z, o3 = a3 * inv + k0.w + b0.w;
    float o4 = a4 * inv + k1.x + b1.x, o5 = a5 * inv + k1.y + b1.y;
    float o6 = a6 * inv + k1.z + b1.z, o7 = a7 * inv + k1.w + b1.w;
    o0 = (o0 > 0.f) ? o0 : NEG * o0;  o1 = (o1 > 0.f) ? o1 : NEG * o1;
    o2 = (o2 > 0.f) ? o2 : NEG * o2;  o3 = (o3 > 0.f) ? o3 : NEG * o3;
    o4 = (o4 > 0.f) ? o4 : NEG * o4;  o5 = (o5 > 0.f) ? o5 : NEG * o5;
    o6 = (o6 > 0.f) ? o6 : NEG * o6;  o7 = (o7 > 0.f) ? o7 : NEG * o7;
    *(float4*)&out[off]     = make_float4(o0, o1, o2, o3);
    *(float4*)&out[off + 4] = make_float4(o4, o5, o6, o7);
}

// ---------------- launch ----------------------------------------------------
extern "C" void kernel_launch(void* const* d_in, const int* in_sizes, int n_in,
                              void* d_out, int out_size)
{
    const float* x      = (const float*)d_in[0];
    const float* W      = (const float*)d_in[1];
    const float* a_src  = (const float*)d_in[2];
    const float* a_trg  = (const float*)d_in[3];
    const float* skip_w = (const float*)d_in[4];
    const float* bias   = (const float*)d_in[5];
    const int*   esrc   = (const int*)d_in[6];
    const int*   etrg   = (const int*)d_in[7];
    float* out = (float*)d_out;

    const int Nn = in_sizes[0] / HF;   // 50000
    const int E  = in_sizes[6];        // 800000

    cudaFuncSetAttribute(gemm_kernel, cudaFuncAttributeMaxDynamicSharedMemorySize, GEMM_SMEM);

    prep_bt_kernel<<<(512 * 256 + 255) / 256, 256>>>(W, skip_w, Nn);

    gemm_kernel<<<(Nn + 127) / 128, 256, GEMM_SMEM>>>(x, Nn);

    int nblk = (Nn * 32 + 255) / 256;
    score_kernel<<<nblk, 256>>>(a_src, a_trg, Nn);

    hist_kernel<<<(E + 255) / 256, 256>>>(etrg, E);
    scan_kernel<<<1, 1024>>>(Nn);
    fill_kernel<<<(E + 255) / 256, 256>>>(esrc, etrg, E);

    agg_kernel<<<nblk, 256>>>(bias, out, Nn);
}

// round 9
// speedup vs baseline: 3.5651x; 1.1249x over previous
#include <cuda_runtime.h>
#include <cuda_fp16.h>
#include <cstdint>

#define MAX_N 50000
#define MAX_E 800000
#define HF    256
#define NH    4
#define NF    64
#define NEG   0.2f

// ---------------- scratch (device globals; no allocations allowed) ----------
__device__ float g_proj [(size_t)MAX_N * HF];
__device__ float g_skipb[(size_t)MAX_N * HF];
__device__ float g_ssrc [MAX_N * NH];
__device__ float g_strg [MAX_N * NH];
__device__ int   g_deg  [MAX_N];
__device__ int   g_rowstart[MAX_N + 1];
__device__ int   g_pos  [MAX_N];
__device__ int   g_csr  [MAX_E];
__device__ __half g_bt[512 * 256];   // [n 0..511][k] = (W | skip_w)^T, fp16

// ---------------- PTX helpers (arch-generic: sm_80-era) ----------------------
__device__ __forceinline__ uint32_t smem_u32(const void* p) {
    uint32_t a;
    asm("{ .reg .u64 t; cvta.to.shared.u64 t, %1; cvt.u32.u64 %0, t; }" : "=r"(a) : "l"(p));
    return a;
}
__device__ __forceinline__ void cp16(uint32_t saddr, const void* g, int srcsize) {
    asm volatile("cp.async.cg.shared.global [%0], [%1], 16, %2;"
                 :: "r"(saddr), "l"(g), "r"(srcsize) : "memory");
}
#define CP_COMMIT() asm volatile("cp.async.commit_group;" ::: "memory")

#define LDSM_X4(d0, d1, d2, d3, addr) \
    asm volatile("ldmatrix.sync.aligned.m8n8.x4.shared.b16 {%0,%1,%2,%3}, [%4];" \
                 : "=r"(d0), "=r"(d1), "=r"(d2), "=r"(d3) : "r"(addr))

__device__ __forceinline__ void mma16816(float* c, const uint32_t* a, const uint32_t* b) {
    asm volatile(
        "mma.sync.aligned.m16n8k16.row.col.f32.f16.f16.f32 "
        "{%0,%1,%2,%3}, {%4,%5,%6,%7}, {%8,%9}, {%0,%1,%2,%3};"
        : "+f"(c[0]), "+f"(c[1]), "+f"(c[2]), "+f"(c[3])
        : "r"(a[0]), "r"(a[1]), "r"(a[2]), "r"(a[3]), "r"(b[0]), "r"(b[1]));
}

// ---------------- weight prep (also zeroes g_deg) -----------------------------
__global__ void prep_bt_kernel(const float* __restrict__ W, const float* __restrict__ skw,
                               int Nn) {
    int i = blockIdx.x * blockDim.x + threadIdx.x;
    if (i < Nn) g_deg[i] = 0;
    if (i < 512 * 256) {
        int n = i >> 8, k = i & 255;
        float v = (n < 256) ? W[k * 256 + n] : skw[k * 256 + (n - 256)];
        g_bt[i] = __float2half_rn(v);
    }
}

// ---------------- HMMA GEMM: C[M,512] = A[M,256] @ BT^T ----------------------
// fp16 2-chain error compensation: A = ah + al (fp16 split), B = bh (fp16).
// acc += ah*bh + al*bh  (element rel err ~2^-11 from B, global ~1e-4).
// A-resident: one CTA owns 128 rows, full K=256 in smem (converted in-kernel
// from fp32 x); loops 4 bn tiles of 128 cols, 3-stage cp.async B pipeline.
#define AP       264      // padded A row stride (elements)
#define SA_HI    0
#define SA_LO    67584
#define SB_BASE  135168
#define SB_STAGE 10240
#define LDB_PAD  40
#define GEMM_SMEM (135168 + 3 * 10240)   // 165888

__device__ __forceinline__ void load_A_convert(char* smem, const float* __restrict__ x,
                                               int bm, int M, int tid) {
#pragma unroll
    for (int it = 0; it < 16; it++) {
        int id = tid + it * 256;          // 0..4095 : 128 rows x 32 chunks(8 floats)
        int r = id >> 5, c = id & 31;
        int gr = bm * 128 + r;
        float4 v0 = make_float4(0.f, 0.f, 0.f, 0.f), v1 = v0;
        if (gr < M) {
            const float* src = x + (size_t)gr * 256 + c * 8;
            v0 = *(const float4*)src;
            v1 = *(const float4*)(src + 4);
        }
        float f[8] = {v0.x, v0.y, v0.z, v0.w, v1.x, v1.y, v1.z, v1.w};
        __half2 hi2[4], lo2[4];
#pragma unroll
        for (int j = 0; j < 4; j++) {
            __half ha = __float2half_rn(f[2 * j]);
            __half hb = __float2half_rn(f[2 * j + 1]);
            hi2[j] = __half2(ha, hb);
            lo2[j] = __half2(__float2half_rn(f[2 * j]     - __half2float(ha)),
                             __float2half_rn(f[2 * j + 1] - __half2float(hb)));
        }
        uint32_t dst = (uint32_t)(r * AP * 2 + c * 16);
        *(uint4*)(smem + SA_HI + dst) = *(uint4*)hi2;
        *(uint4*)(smem + SA_LO + dst) = *(uint4*)lo2;
    }
}
// B stage: 128 rows x 32 cols fp16 = 8 KB payload (padded rows LDB_PAD=40).
// 512 16B-chunks, 256 threads -> 2 chunks per thread.
__device__ __forceinline__ void issue_B(uint32_t sb, int g, int tid) {
    int bn = g >> 3, ks = g & 7;
    uint32_t base = sb + SB_BASE + (uint32_t)(g % 3) * SB_STAGE;
    int row = tid >> 1;
#pragma unroll
    for (int j = 0; j < 2; j++) {
        int chunk = (tid & 1) * 2 + j;               // 0..3
        int gcol  = ks * 32 + chunk * 8;
        int gn    = bn * 128 + row;
        uint32_t dst = (uint32_t)(row * LDB_PAD * 2 + chunk * 16);
        cp16(base + dst, &g_bt[(size_t)gn * 256 + gcol], 16);
    }
}

__global__ __launch_bounds__(256, 1) void gemm_kernel(const float* __restrict__ x, int M)
{
    extern __shared__ __align__(16) char smem[];
    const uint32_t sb = smem_u32(smem);
    const int tid  = threadIdx.x;
    const int wid  = tid >> 5;
    const int lane = tid & 31;
    const int bm   = blockIdx.x;

    const int wm = (wid >> 2) * 64;   // warp m offset (0 / 64)
    const int wn = (wid & 3) * 32;    // warp n offset (0/32/64/96)

    float acc[4][4][4];
#pragma unroll
    for (int i = 0; i < 4; i++)
#pragma unroll
        for (int j = 0; j < 4; j++)
#pragma unroll
            for (int q = 0; q < 4; q++) acc[i][j][q] = 0.f;

    const int g8 = lane >> 3;    // ldmatrix address group 0..3
    const int r8 = lane & 7;

    issue_B(sb, 0, tid);
    CP_COMMIT();
    issue_B(sb, 1, tid);
    CP_COMMIT();
    load_A_convert(smem, x, bm, M, tid);

#pragma unroll 1
    for (int g = 0; g < 32; g++) {
        if (g + 2 < 32) {
            issue_B(sb, g + 2, tid);
            CP_COMMIT();
            asm volatile("cp.async.wait_group 2;" ::: "memory");
        } else if (g + 1 < 32) {
            asm volatile("cp.async.wait_group 1;" ::: "memory");
        } else {
            asm volatile("cp.async.wait_group 0;" ::: "memory");
        }
        __syncthreads();

        const int bn = g >> 3, ks = g & 7;
        const uint32_t stB = sb + SB_BASE + (uint32_t)(g % 3) * SB_STAGE;
#pragma unroll
        for (int k16 = 0; k16 < 32; k16 += 16) {
            uint32_t ah[4][4], al[4][4], bh[4][2];
            // A frags from resident tile
            {
                int arow = wm + (g8 & 1) * 8 + r8;
                int acol = ks * 32 + k16 + (g8 >> 1) * 8;
                uint32_t aoff = (uint32_t)(arow * AP + acol) * 2;
#pragma unroll
                for (int mi = 0; mi < 4; mi++) {
                    uint32_t ad = sb + aoff + (uint32_t)(mi * 16 * AP * 2);
                    LDSM_X4(ah[mi][0], ah[mi][1], ah[mi][2], ah[mi][3], ad + SA_HI);
                    LDSM_X4(al[mi][0], al[mi][1], al[mi][2], al[mi][3], ad + SA_LO);
                }
            }
            // B frags from stage buffer
            {
                int brow = wn + (g8 >> 1) * 8 + r8;
                int bcol = k16 + (g8 & 1) * 8;
                uint32_t boff = (uint32_t)(brow * LDB_PAD + bcol) * 2;
#pragma unroll
                for (int j = 0; j < 2; j++) {
                    uint32_t bd = stB + boff + (uint32_t)(j * 16 * LDB_PAD * 2);
                    LDSM_X4(bh[2 * j][0], bh[2 * j][1], bh[2 * j + 1][0], bh[2 * j + 1][1],
                            bd);
                }
            }
#pragma unroll
            for (int mi = 0; mi < 4; mi++)
#pragma unroll
                for (int ni = 0; ni < 4; ni++) {
                    mma16816(acc[mi][ni], ah[mi], bh[ni]);
                    mma16816(acc[mi][ni], al[mi], bh[ni]);
                }
        }
        __syncthreads();

        if (ks == 7) {
            float* dst = (bn < 2) ? g_proj : g_skipb;
            const int colbase = (bn & 1) * 128 + wn;
#pragma unroll
            for (int mi = 0; mi < 4; mi++) {
                int gr = bm * 128 + wm + mi * 16 + (lane >> 2);
#pragma unroll
                for (int ni = 0; ni < 4; ni++) {
                    int gc = colbase + ni * 8 + (lane & 3) * 2;
                    if (gr < M)
                        *(float2*)&dst[(size_t)gr * 256 + gc] =
                            make_float2(acc[mi][ni][0], acc[mi][ni][1]);
                    if (gr + 8 < M)
                        *(float2*)&dst[(size_t)(gr + 8) * 256 + gc] =
                            make_float2(acc[mi][ni][2], acc[mi][ni][3]);
                    acc[mi][ni][0] = acc[mi][ni][1] = acc[mi][ni][2] = acc[mi][ni][3] = 0.f;
                }
            }
        }
    }
}

// ---------------- attention scores: one warp per node, 4 heads --------------
__global__ void score_kernel(const float* __restrict__ a_src,
                             const float* __restrict__ a_trg, int Nn)
{
    int w    = (blockIdx.x * blockDim.x + threadIdx.x) >> 5;
    int lane = threadIdx.x & 31;
    if (w >= Nn) return;
    int h = lane >> 3, q = lane & 7;

    const float* pr = g_proj + (size_t)w * HF + lane * 8;
    float4 p0 = *(const float4*)pr;
    float4 p1 = *(const float4*)(pr + 4);
    float4 s0 = *(const float4*)(a_src + lane * 8);
    float4 s1 = *(const float4*)(a_src + lane * 8 + 4);
    float4 t0 = *(const float4*)(a_trg + lane * 8);
    float4 t1 = *(const float4*)(a_trg + lane * 8 + 4);

    float ss = p0.x * s0.x + p0.y * s0.y + p0.z * s0.z + p0.w * s0.w
             + p1.x * s1.x + p1.y * s1.y + p1.z * s1.z + p1.w * s1.w;
    float st = p0.x * t0.x + p0.y * t0.y + p0.z * t0.z + p0.w * t0.w
             + p1.x * t1.x + p1.y * t1.y + p1.z * t1.z + p1.w * t1.w;
#pragma unroll
    for (int o = 4; o; o >>= 1) {
        ss += __shfl_xor_sync(0xffffffffu, ss, o);
        st += __shfl_xor_sync(0xffffffffu, st, o);
    }
    if (q == 0) {
        g_ssrc[w * NH + h] = ss;
        g_strg[w * NH + h] = st;
    }
}

// ---------------- CSR construction ------------------------------------------
__global__ void hist_kernel(const int* __restrict__ etrg, int E)
{
    int e = blockIdx.x * blockDim.x + threadIdx.x;
    if (e < E) atomicAdd(&g_deg[etrg[e]], 1);
}
__global__ void scan_kernel(int Nn)
{
    __shared__ int warpsum[32];
    __shared__ int s_carry;
    const int t = threadIdx.x, lane = t & 31, wid = t >> 5;
    if (t == 0) s_carry = 0;
    __syncthreads();
    for (int base = 0; base < Nn; base += 4096) {
        int i0 = base + t * 4;
        int v[4];
#pragma unroll
        for (int j = 0; j < 4; j++) v[j] = (i0 + j < Nn) ? g_deg[i0 + j] : 0;
        int tsum = v[0] + v[1] + v[2] + v[3];
        int x = tsum;
#pragma unroll
        for (int o = 1; o < 32; o <<= 1) {
            int y = __shfl_up_sync(0xffffffffu, x, o);
            if (lane >= o) x += y;
        }
        if (lane == 31) warpsum[wid] = x;
        __syncthreads();
        if (wid == 0) {
            int wv = warpsum[lane];
            int xx = wv;
#pragma unroll
            for (int o = 1; o < 32; o <<= 1) {
                int y = __shfl_up_sync(0xffffffffu, xx, o);
                if (lane >= o) xx += y;
            }
            warpsum[lane] = xx - wv;
        }
        __syncthreads();
        int run = s_carry + warpsum[wid] + (x - tsum);
#pragma unroll
        for (int j = 0; j < 4; j++) {
            if (i0 + j < Nn) { g_rowstart[i0 + j] = run; g_pos[i0 + j] = run; }
            run += v[j];
        }
        __syncthreads();
        if (t == 1023) s_carry = run;
        __syncthreads();
    }
    if (t == 0) g_rowstart[Nn] = s_carry;
}
__global__ void fill_kernel(const int* __restrict__ esrc,
                            const int* __restrict__ etrg, int E)
{
    int e = blockIdx.x * blockDim.x + threadIdx.x;
    if (e < E) {
        int tnode = etrg[e];
        int p = atomicAdd(&g_pos[tnode], 1);
        g_csr[p] = esrc[e];
    }
}

// ---------------- aggregation: single pass, owner-computed weights ----------
__global__ void agg_kernel(const float* __restrict__ bias,
                           float* __restrict__ out, int Nn)
{
    int w    = (blockIdx.x * blockDim.x + threadIdx.x) >> 5;
    int lane = threadIdx.x & 31;
    if (w >= Nn) return;
    const int h = lane >> 3, q = lane & 7;
    const int hb = h << 3;

    const int s0 = g_rowstart[w];
    const int s1 = g_rowstart[w + 1];
    const float strg = g_strg[w * NH + h];

    float denom = 0.f;
    float a0 = 0.f, a1 = 0.f, a2 = 0.f, a3 = 0.f, a4 = 0.f, a5 = 0.f, a6 = 0.f, a7 = 0.f;

    int i = s0;
    for (; i + 8 <= s1; i += 8) {
        int   sq = g_csr[i + q];
        float e  = g_ssrc[sq * NH + h] + strg;
        e = (e > 0.f) ? e : NEG * e;
        float wq = __expf(e);
        denom += wq;
#pragma unroll
        for (int j = 0; j < 8; j++) {
            float wgt = __shfl_sync(0xffffffffu, wq, hb + j);
            int   s   = __shfl_sync(0xffffffffu, sq, j);
            const float* pr = g_proj + (size_t)s * HF + lane * 8;
            float4 p0 = *(const float4*)pr;
            float4 p1 = *(const float4*)(pr + 4);
            a0 += wgt * p0.x; a1 += wgt * p0.y; a2 += wgt * p0.z; a3 += wgt * p0.w;
            a4 += wgt * p1.x; a5 += wgt * p1.y; a6 += wgt * p1.z; a7 += wgt * p1.w;
        }
    }
    if (i < s1) {
        int nb = s1 - i;
        float wq = 0.f;
        int   sq = 0;
        if (q < nb) {
            sq = g_csr[i + q];
            float e = g_ssrc[sq * NH + h] + strg;
            e = (e > 0.f) ? e : NEG * e;
            wq = __expf(e);
        }
        denom += wq;
        for (int j = 0; j < nb; j++) {
            float wgt = __shfl_sync(0xffffffffu, wq, hb + j);
            int   s   = __shfl_sync(0xffffffffu, sq, j);
            const float* pr = g_proj + (size_t)s * HF + lane * 8;
            float4 p0 = *(const float4*)pr;
            float4 p1 = *(const float4*)(pr + 4);
            a0 += wgt * p0.x; a1 += wgt * p0.y; a2 += wgt * p0.z; a3 += wgt * p0.w;
            a4 += wgt * p1.x; a5 += wgt * p1.y; a6 += wgt * p1.z; a7 += wgt * p1.w;
        }
    }

    denom += __shfl_xor_sync(0xffffffffu, denom, 4);
    denom += __shfl_xor_sync(0xffffffffu, denom, 2);
    denom += __shfl_xor_sync(0xffffffffu, denom, 1);
    const float inv = 1.f / (denom + 1e-16f);

    const size_t off = (size_t)w * HF + lane * 8;
    float4 k0 = *(const float4*)&g_skipb[off];
    float4 k1 = *(const float4*)&g_skipb[off + 4];
    float4 b0 = *(const float4*)&bias[lane * 8];
    float4 b1 = *(const float4*)&bias[lane * 8 + 4];
    float o0 = a0 * inv + k0.x + b0.x, o1 = a1 * inv + k0.y + b0.y;
    float o2 = a2 * inv + k0.z + b0.z, o3 = a3 * inv + k0.w + b0.w;
    float o4 = a4 * inv + k1.x + b1.x, o5 = a5 * inv + k1.y + b1.y;
    float o6 = a6 * inv + k1.z + b1.z, o7 = a7 * inv + k1.w + b1.w;
    o0 = (o0 > 0.f) ? o0 : NEG * o0;  o1 = (o1 > 0.f) ? o1 : NEG * o1;
    o2 = (o2 > 0.f) ? o2 : NEG * o2;  o3 = (o3 > 0.f) ? o3 : NEG * o3;
    o4 = (o4 > 0.f) ? o4 : NEG * o4;  o5 = (o5 > 0.f) ? o5 : NEG * o5;
    o6 = (o6 > 0.f) ? o6 : NEG * o6;  o7 = (o7 > 0.f) ? o7 : NEG * o7;
    *(float4*)&out[off]     = make_float4(o0, o1, o2, o3);
    *(float4*)&out[off + 4] = make_float4(o4, o5, o6, o7);
}

// ---------------- launch ----------------------------------------------------
extern "C" void kernel_launch(void* const* d_in, const int* in_sizes, int n_in,
                              void* d_out, int out_size)
{
    const float* x      = (const float*)d_in[0];
    const float* W      = (const float*)d_in[1];
    const float* a_src  = (const float*)d_in[2];
    const float* a_trg  = (const float*)d_in[3];
    const float* skip_w = (const float*)d_in[4];
    const float* bias   = (const float*)d_in[5];
    const int*   esrc   = (const int*)d_in[6];
    const int*   etrg   = (const int*)d_in[7];
    float* out = (float*)d_out;

    const int Nn = in_sizes[0] / HF;   // 50000
    const int E  = in_sizes[6];        // 800000

    cudaFuncSetAttribute(gemm_kernel, cudaFuncAttributeMaxDynamicSharedMemorySize, GEMM_SMEM);

    prep_bt_kernel<<<(512 * 256 + 255) / 256, 256>>>(W, skip_w, Nn);

    gemm_kernel<<<(Nn + 127) / 128, 256, GEMM_SMEM>>>(x, Nn);

    int nblk = (Nn * 32 + 255) / 256;
    score_kernel<<<nblk, 256>>>(a_src, a_trg, Nn);

    hist_kernel<<<(E + 255) / 256, 256>>>(etrg, E);
    scan_kernel<<<1, 1024>>>(Nn);
    fill_kernel<<<(E + 255) / 256, 256>>>(esrc, etrg, E);

    agg_kernel<<<nblk, 256>>>(bias, out, Nn);
}

// round 11
// speedup vs baseline: 3.8805x; 1.0885x over previous
#include <cuda_runtime.h>
#include <cuda_fp16.h>
#include <cstdint>

#define MAX_N 50000
#define MAX_E 800000
#define HF    256
#define NH    4
#define NF    64
#define NEG   0.2f

// ---------------- scratch (device globals; no allocations allowed) ----------
__device__ float g_proj [(size_t)MAX_N * HF];
__device__ float g_skipb[(size_t)MAX_N * HF];
__device__ float g_ssrc [MAX_N * NH];
__device__ float g_strg [MAX_N * NH];
__device__ int   g_deg  [MAX_N];
__device__ int   g_rowstart[MAX_N + 1];
__device__ int   g_pos  [MAX_N];
__device__ int   g_csr  [MAX_E];
__device__ __half g_bt[512 * 256];   // [n 0..511][k] = (W | skip_w)^T, fp16

// ---------------- PTX helpers (arch-generic: sm_80-era) ----------------------
__device__ __forceinline__ uint32_t smem_u32(const void* p) {
    uint32_t a;
    asm("{ .reg .u64 t; cvta.to.shared.u64 t, %1; cvt.u32.u64 %0, t; }" : "=r"(a) : "l"(p));
    return a;
}
__device__ __forceinline__ void cp16(uint32_t saddr, const void* g, int srcsize) {
    asm volatile("cp.async.cg.shared.global [%0], [%1], 16, %2;"
                 :: "r"(saddr), "l"(g), "r"(srcsize) : "memory");
}
#define CP_COMMIT() asm volatile("cp.async.commit_group;" ::: "memory")

#define LDSM_X4(d0, d1, d2, d3, addr) \
    asm volatile("ldmatrix.sync.aligned.m8n8.x4.shared.b16 {%0,%1,%2,%3}, [%4];" \
                 : "=r"(d0), "=r"(d1), "=r"(d2), "=r"(d3) : "r"(addr))

__device__ __forceinline__ void mma16816(float* c, const uint32_t* a, const uint32_t* b) {
    asm volatile(
        "mma.sync.aligned.m16n8k16.row.col.f32.f16.f16.f32 "
        "{%0,%1,%2,%3}, {%4,%5,%6,%7}, {%8,%9}, {%0,%1,%2,%3};"
        : "+f"(c[0]), "+f"(c[1]), "+f"(c[2]), "+f"(c[3])
        : "r"(a[0]), "r"(a[1]), "r"(a[2]), "r"(a[3]), "r"(b[0]), "r"(b[1]));
}

// ---------------- weight prep (also zeroes g_deg) -----------------------------
__global__ void prep_bt_kernel(const float* __restrict__ W, const float* __restrict__ skw,
                               int Nn) {
    int i = blockIdx.x * blockDim.x + threadIdx.x;
    if (i < Nn) g_deg[i] = 0;
    if (i < 512 * 256) {
        int n = i >> 8, k = i & 255;
        float v = (n < 256) ? W[k * 256 + n] : skw[k * 256 + (n - 256)];
        g_bt[i] = __float2half_rn(v);
    }
}

// ---------------- HMMA GEMM: C[M,512] = A[M,256] @ BT^T ----------------------
// fp16 2-chain error compensation: A = ah + al (fp16 split), B = bh (fp16).
// acc += ah*bh + al*bh.  A-resident (full K=256 in smem); 4 bn tiles of 128
// cols, 3-stage cp.async B pipeline. Attention scores (proj . a_src/a_trg)
// fused into the bn 0/1 epilogues via smem accumulation.
#define AP       264      // padded A row stride (elements)
#define SA_HI    0
#define SA_LO    67584
#define SB_BASE  135168
#define SB_STAGE 10240
#define LDB_PAD  40
#define SC_OFF   165888   // score buffer: 128 rows x 4 heads x 2 = 1024 floats
#define GEMM_SMEM (165888 + 4096)   // 169984

__device__ __forceinline__ void load_A_convert(char* smem, const float* __restrict__ x,
                                               int bm, int M, int tid) {
#pragma unroll
    for (int it = 0; it < 16; it++) {
        int id = tid + it * 256;          // 0..4095 : 128 rows x 32 chunks(8 floats)
        int r = id >> 5, c = id & 31;
        int gr = bm * 128 + r;
        float4 v0 = make_float4(0.f, 0.f, 0.f, 0.f), v1 = v0;
        if (gr < M) {
            const float* src = x + (size_t)gr * 256 + c * 8;
            v0 = *(const float4*)src;
            v1 = *(const float4*)(src + 4);
        }
        float f[8] = {v0.x, v0.y, v0.z, v0.w, v1.x, v1.y, v1.z, v1.w};
        __half2 hi2[4], lo2[4];
#pragma unroll
        for (int j = 0; j < 4; j++) {
            __half ha = __float2half_rn(f[2 * j]);
            __half hb = __float2half_rn(f[2 * j + 1]);
            hi2[j] = __half2(ha, hb);
            lo2[j] = __half2(__float2half_rn(f[2 * j]     - __half2float(ha)),
                             __float2half_rn(f[2 * j + 1] - __half2float(hb)));
        }
        uint32_t dst = (uint32_t)(r * AP * 2 + c * 16);
        *(uint4*)(smem + SA_HI + dst) = *(uint4*)hi2;
        *(uint4*)(smem + SA_LO + dst) = *(uint4*)lo2;
    }
}
__device__ __forceinline__ void issue_B(uint32_t sb, int g, int tid) {
    int bn = g >> 3, ks = g & 7;
    uint32_t base = sb + SB_BASE + (uint32_t)(g % 3) * SB_STAGE;
    int row = tid >> 1;
#pragma unroll
    for (int j = 0; j < 2; j++) {
        int chunk = (tid & 1) * 2 + j;               // 0..3
        int gcol  = ks * 32 + chunk * 8;
        int gn    = bn * 128 + row;
        uint32_t dst = (uint32_t)(row * LDB_PAD * 2 + chunk * 16);
        cp16(base + dst, &g_bt[(size_t)gn * 256 + gcol], 16);
    }
}

__global__ __launch_bounds__(256, 1) void gemm_kernel(const float* __restrict__ x,
                                                      const float* __restrict__ a_src,
                                                      const float* __restrict__ a_trg,
                                                      int M)
{
    extern __shared__ __align__(16) char smem[];
    const uint32_t sb = smem_u32(smem);
    float* s_sc = (float*)(smem + SC_OFF);
    const int tid  = threadIdx.x;
    const int wid  = tid >> 5;
    const int lane = tid & 31;
    const int bm   = blockIdx.x;

    const int wm = (wid >> 2) * 64;   // warp m offset (0 / 64)
    const int wn = (wid & 3) * 32;    // warp n offset (0/32/64/96)

    float acc[4][4][4];
#pragma unroll
    for (int i = 0; i < 4; i++)
#pragma unroll
        for (int j = 0; j < 4; j++)
#pragma unroll
            for (int q = 0; q < 4; q++) acc[i][j][q] = 0.f;

    const int g8 = lane >> 3;    // ldmatrix address group 0..3
    const int r8 = lane & 7;

    issue_B(sb, 0, tid);
    CP_COMMIT();
    issue_B(sb, 1, tid);
    CP_COMMIT();
    load_A_convert(smem, x, bm, M, tid);
    for (int v = tid; v < 1024; v += 256) s_sc[v] = 0.f;

#pragma unroll 1
    for (int g = 0; g < 32; g++) {
        if (g + 2 < 32) {
            issue_B(sb, g + 2, tid);
            CP_COMMIT();
            asm volatile("cp.async.wait_group 2;" ::: "memory");
        } else if (g + 1 < 32) {
            asm volatile("cp.async.wait_group 1;" ::: "memory");
        } else {
            asm volatile("cp.async.wait_group 0;" ::: "memory");
        }
        __syncthreads();

        const int bn = g >> 3, ks = g & 7;
        const uint32_t stB = sb + SB_BASE + (uint32_t)(g % 3) * SB_STAGE;
#pragma unroll
        for (int k16 = 0; k16 < 32; k16 += 16) {
            uint32_t ah[4][4], al[4][4], bh[4][2];
            {
                int arow = wm + (g8 & 1) * 8 + r8;
                int acol = ks * 32 + k16 + (g8 >> 1) * 8;
                uint32_t aoff = (uint32_t)(arow * AP + acol) * 2;
#pragma unroll
                for (int mi = 0; mi < 4; mi++) {
                    uint32_t ad = sb + aoff + (uint32_t)(mi * 16 * AP * 2);
                    LDSM_X4(ah[mi][0], ah[mi][1], ah[mi][2], ah[mi][3], ad + SA_HI);
                    LDSM_X4(al[mi][0], al[mi][1], al[mi][2], al[mi][3], ad + SA_LO);
                }
            }
            {
                int brow = wn + (g8 >> 1) * 8 + r8;
                int bcol = k16 + (g8 & 1) * 8;
                uint32_t boff = (uint32_t)(brow * LDB_PAD + bcol) * 2;
#pragma unroll
                for (int j = 0; j < 2; j++) {
                    uint32_t bd = stB + boff + (uint32_t)(j * 16 * LDB_PAD * 2);
                    LDSM_X4(bh[2 * j][0], bh[2 * j][1], bh[2 * j + 1][0], bh[2 * j + 1][1],
                            bd);
                }
            }
#pragma unroll
            for (int mi = 0; mi < 4; mi++)
#pragma unroll
                for (int ni = 0; ni < 4; ni++) {
                    mma16816(acc[mi][ni], ah[mi], bh[ni]);
                    mma16816(acc[mi][ni], al[mi], bh[ni]);
                }
        }
        __syncthreads();

        if (ks == 7) {
            float* dst = (bn < 2) ? g_proj : g_skipb;
            const int colbase = (bn & 1) * 128 + wn;

            // fused attention scores for proj tiles (bn 0,1): global col == flat
            // index into a_src/a_trg ([H,F] contiguous, 256 floats).
            if (bn < 2) {
                const int h = colbase >> 6;     // all 8 cols of a thread share a head
#pragma unroll
                for (int mi = 0; mi < 4; mi++) {
                    int rl = wm + mi * 16 + (lane >> 2);
                    float s0 = 0.f, t0 = 0.f, s1 = 0.f, t1 = 0.f;
#pragma unroll
                    for (int ni = 0; ni < 4; ni++) {
                        int gc = colbase + ni * 8 + (lane & 3) * 2;
                        float as0 = a_src[gc], as1 = a_src[gc + 1];
                        float at0 = a_trg[gc], at1 = a_trg[gc + 1];
                        s0 += acc[mi][ni][0] * as0 + acc[mi][ni][1] * as1;
                        t0 += acc[mi][ni][0] * at0 + acc[mi][ni][1] * at1;
                        s1 += acc[mi][ni][2] * as0 + acc[mi][ni][3] * as1;
                        t1 += acc[mi][ni][2] * at0 + acc[mi][ni][3] * at1;
                    }
                    atomicAdd(&s_sc[rl * 8 + h * 2 + 0], s0);
                    atomicAdd(&s_sc[rl * 8 + h * 2 + 1], t0);
                    atomicAdd(&s_sc[(rl + 8) * 8 + h * 2 + 0], s1);
                    atomicAdd(&s_sc[(rl + 8) * 8 + h * 2 + 1], t1);
                }
            }

#pragma unroll
            for (int mi = 0; mi < 4; mi++) {
                int gr = bm * 128 + wm + mi * 16 + (lane >> 2);
#pragma unroll
                for (int ni = 0; ni < 4; ni++) {
                    int gc = colbase + ni * 8 + (lane & 3) * 2;
                    if (gr < M)
                        *(float2*)&dst[(size_t)gr * 256 + gc] =
                            make_float2(acc[mi][ni][0], acc[mi][ni][1]);
                    if (gr + 8 < M)
                        *(float2*)&dst[(size_t)(gr + 8) * 256 + gc] =
                            make_float2(acc[mi][ni][2], acc[mi][ni][3]);
                    acc[mi][ni][0] = acc[mi][ni][1] = acc[mi][ni][2] = acc[mi][ni][3] = 0.f;
                }
            }

            if (bn == 1) {
                __syncthreads();                 // all score atomics done
                for (int v = tid; v < 512; v += 256) {
                    int r = v >> 2, hh = v & 3;
                    int gr2 = bm * 128 + r;
                    if (gr2 < M) {
                        g_ssrc[gr2 * NH + hh] = s_sc[r * 8 + hh * 2];
                        g_strg[gr2 * NH + hh] = s_sc[r * 8 + hh * 2 + 1];
                    }
                }
            }
        }
    }
}

// ---------------- CSR construction ------------------------------------------
__global__ void hist_kernel(const int* __restrict__ etrg, int E)
{
    int e = blockIdx.x * blockDim.x + threadIdx.x;
    if (e < E) atomicAdd(&g_deg[etrg[e]], 1);
}
__global__ void scan_kernel(int Nn)
{
    __shared__ int warpsum[32];
    __shared__ int s_carry;
    const int t = threadIdx.x, lane = t & 31, wid = t >> 5;
    if (t == 0) s_carry = 0;
    __syncthreads();
    for (int base = 0; base < Nn; base += 4096) {
        int i0 = base + t * 4;
        int v[4];
#pragma unroll
        for (int j = 0; j < 4; j++) v[j] = (i0 + j < Nn) ? g_deg[i0 + j] : 0;
        int tsum = v[0] + v[1] + v[2] + v[3];
        int x = tsum;
#pragma unroll
        for (int o = 1; o < 32; o <<= 1) {
            int y = __shfl_up_sync(0xffffffffu, x, o);
            if (lane >= o) x += y;
        }
        if (lane == 31) warpsum[wid] = x;
        __syncthreads();
        if (wid == 0) {
            int wv = warpsum[lane];
            int xx = wv;
#pragma unroll
            for (int o = 1; o < 32; o <<= 1) {
                int y = __shfl_up_sync(0xffffffffu, xx, o);
                if (lane >= o) xx += y;
            }
            warpsum[lane] = xx - wv;
        }
        __syncthreads();
        int run = s_carry + warpsum[wid] + (x - tsum);
#pragma unroll
        for (int j = 0; j < 4; j++) {
            if (i0 + j < Nn) { g_rowstart[i0 + j] = run; g_pos[i0 + j] = run; }
            run += v[j];
        }
        __syncthreads();
        if (t == 1023) s_carry = run;
        __syncthreads();
    }
    if (t == 0) g_rowstart[Nn] = s_carry;
}
__global__ void fill_kernel(const int* __restrict__ esrc,
                            const int* __restrict__ etrg, int E)
{
    int e = blockIdx.x * blockDim.x + threadIdx.x;
    if (e < E) {
        int tnode = etrg[e];
        int p = atomicAdd(&g_pos[tnode], 1);
        g_csr[p] = esrc[e];
    }
}

// ---------------- aggregation: single pass, owner-computed weights ----------
__global__ void agg_kernel(const float* __restrict__ bias,
                           float* __restrict__ out, int Nn)
{
    int w    = (blockIdx.x * blockDim.x + threadIdx.x) >> 5;
    int lane = threadIdx.x & 31;
    if (w >= Nn) return;
    const int h = lane >> 3, q = lane & 7;
    const int hb = h << 3;

    const int s0 = g_rowstart[w];
    const int s1 = g_rowstart[w + 1];
    const float strg = g_strg[w * NH + h];

    float denom = 0.f;
    float a0 = 0.f, a1 = 0.f, a2 = 0.f, a3 = 0.f, a4 = 0.f, a5 = 0.f, a6 = 0.f, a7 = 0.f;

    int i = s0;
    for (; i + 8 <= s1; i += 8) {
        int   sq = g_csr[i + q];
        float e  = g_ssrc[sq * NH + h] + strg;
        e = (e > 0.f) ? e : NEG * e;
        float wq = __expf(e);
        denom += wq;
#pragma unroll
        for (int j = 0; j < 8; j++) {
            float wgt = __shfl_sync(0xffffffffu, wq, hb + j);
            int   s   = __shfl_sync(0xffffffffu, sq, j);
            const float* pr = g_proj + (size_t)s * HF + lane * 8;
            float4 p0 = *(const float4*)pr;
            float4 p1 = *(const float4*)(pr + 4);
            a0 += wgt * p0.x; a1 += wgt * p0.y; a2 += wgt * p0.z; a3 += wgt * p0.w;
            a4 += wgt * p1.x; a5 += wgt * p1.y; a6 += wgt * p1.z; a7 += wgt * p1.w;
        }
    }
    if (i < s1) {
        int nb = s1 - i;
        float wq = 0.f;
        int   sq = 0;
        if (q < nb) {
            sq = g_csr[i + q];
            float e = g_ssrc[sq * NH + h] + strg;
            e = (e > 0.f) ? e : NEG * e;
            wq = __expf(e);
        }
        denom += wq;
        for (int j = 0; j < nb; j++) {
            float wgt = __shfl_sync(0xffffffffu, wq, hb + j);
            int   s   = __shfl_sync(0xffffffffu, sq, j);
            const float* pr = g_proj + (size_t)s * HF + lane * 8;
            float4 p0 = *(const float4*)pr;
            float4 p1 = *(const float4*)(pr + 4);
            a0 += wgt * p0.x; a1 += wgt * p0.y; a2 += wgt * p0.z; a3 += wgt * p0.w;
            a4 += wgt * p1.x; a5 += wgt * p1.y; a6 += wgt * p1.z; a7 += wgt * p1.w;
        }
    }

    denom += __shfl_xor_sync(0xffffffffu, denom, 4);
    denom += __shfl_xor_sync(0xffffffffu, denom, 2);
    denom += __shfl_xor_sync(0xffffffffu, denom, 1);
    const float inv = 1.f / (denom + 1e-16f);

    const size_t off = (size_t)w * HF + lane * 8;
    float4 k0 = *(const float4*)&g_skipb[off];
    float4 k1 = *(const float4*)&g_skipb[off + 4];
    float4 b0 = *(const float4*)&bias[lane * 8];
    float4 b1 = *(const float4*)&bias[lane * 8 + 4];
    float o0 = a0 * inv + k0.x + b0.x, o1 = a1 * inv + k0.y + b0.y;
    float o2 = a2 * inv + k0.z + b0.z, o3 = a3 * inv + k0.w + b0.w;
    float o4 = a4 * inv + k1.x + b1.x, o5 = a5 * inv + k1.y + b1.y;
    float o6 = a6 * inv + k1.z + b1.z, o7 = a7 * inv + k1.w + b1.w;
    o0 = (o0 > 0.f) ? o0 : NEG * o0;  o1 = (o1 > 0.f) ? o1 : NEG * o1;
    o2 = (o2 > 0.f) ? o2 : NEG * o2;  o3 = (o3 > 0.f) ? o3 : NEG * o3;
    o4 = (o4 > 0.f) ? o4 : NEG * o4;  o5 = (o5 > 0.f) ? o5 : NEG * o5;
    o6 = (o6 > 0.f) ? o6 : NEG * o6;  o7 = (o7 > 0.f) ? o7 : NEG * o7;
    *(float4*)&out[off]     = make_float4(o0, o1, o2, o3);
    *(float4*)&out[off + 4] = make_float4(o4, o5, o6, o7);
}

// ---------------- launch ----------------------------------------------------
extern "C" void kernel_launch(void* const* d_in, const int* in_sizes, int n_in,
                              void* d_out, int out_size)
{
    const float* x      = (const float*)d_in[0];
    const float* W      = (const float*)d_in[1];
    const float* a_src  = (const float*)d_in[2];
    const float* a_trg  = (const float*)d_in[3];
    const float* skip_w = (const float*)d_in[4];
    const float* bias   = (const float*)d_in[5];
    const int*   esrc   = (const int*)d_in[6];
    const int*   etrg   = (const int*)d_in[7];
    float* out = (float*)d_out;

    const int Nn = in_sizes[0] / HF;   // 50000
    const int E  = in_sizes[6];        // 800000

    cudaFuncSetAttribute(gemm_kernel, cudaFuncAttributeMaxDynamicSharedMemorySize, GEMM_SMEM);

    // fork-join: CSR chain (hist/scan/fill) overlaps the GEMM on a side stream
    cudaStream_t s_side;
    cudaEvent_t ev_fork, ev_join;
    cudaStreamCreateWithFlags(&s_side, cudaStreamNonBlocking);
    cudaEventCreateWithFlags(&ev_fork, cudaEventDisableTiming);
    cudaEventCreateWithFlags(&ev_join, cudaEventDisableTiming);

    prep_bt_kernel<<<(512 * 256 + 255) / 256, 256>>>(W, skip_w, Nn);   // zeroes g_deg

    cudaEventRecord(ev_fork, 0);
    cudaStreamWaitEvent(s_side, ev_fork, 0);
    hist_kernel<<<(E + 255) / 256, 256, 0, s_side>>>(etrg, E);
    scan_kernel<<<1, 1024, 0, s_side>>>(Nn);
    fill_kernel<<<(E + 255) / 256, 256, 0, s_side>>>(esrc, etrg, E);
    cudaEventRecord(ev_join, s_side);

    gemm_kernel<<<(Nn + 127) / 128, 256, GEMM_SMEM>>>(x, a_src, a_trg, Nn);

    cudaStreamWaitEvent(0, ev_join, 0);
    int nblk = (Nn * 32 + 255) / 256;
    agg_kernel<<<nblk, 256>>>(bias, out, Nn);

    // release handles (host-side objects; graph retains captured dependencies)
    cudaEventDestroy(ev_fork);
    cudaEventDestroy(ev_join);
    cudaStreamDestroy(s_side);
}